// round 11
// baseline (speedup 1.0000x reference)
#include <cuda_runtime.h>
#include <cuda_bf16.h>
#include <cstdint>
#include <math.h>

// Problem constants (fixed by the dataset)
#define Bb   2
#define Ll   2048
#define Dm   1024
#define Hh   16
#define DhD  64
#define PAD  1536
#define Mrows (Bb * Ll)          // 4096
#define QKVN  (3 * Dm)           // 3072

// ---------------------------------------------------------------------------
// Scratch (device globals; no runtime allocation allowed)
// ---------------------------------------------------------------------------
__device__ __nv_bfloat16 g_ah[(size_t)Mrows * Dm];
__device__ __nv_bfloat16 g_al[(size_t)Mrows * Dm];
__device__ __nv_bfloat16 g_bh[(size_t)QKVN * Dm];
__device__ __nv_bfloat16 g_bl[(size_t)QKVN * Dm];
#define QKVSZ ((size_t)Bb * Hh * Ll * DhD)
__device__ __nv_bfloat16 g_qh[QKVSZ], g_ql[QKVSZ];
__device__ __nv_bfloat16 g_kh[QKVSZ], g_kl[QKVSZ];
__device__ __nv_bfloat16 g_vh[QKVSZ], g_vl[QKVSZ];
__device__ float2 g_rope[Ll * 32];

// ---------------------------------------------------------------------------
// mma.sync helpers
// ---------------------------------------------------------------------------
__device__ __forceinline__ uint32_t smem_u32(const void* p) {
    uint32_t a;
    asm("{ .reg .u64 t; cvta.to.shared.u64 t, %1; cvt.u32.u64 %0, t; }" : "=r"(a) : "l"(p));
    return a;
}
__device__ __forceinline__ void ldsm_x4(uint32_t r[4], uint32_t addr) {
    asm volatile("ldmatrix.sync.aligned.m8n8.x4.shared.b16 {%0,%1,%2,%3}, [%4];"
                 : "=r"(r[0]), "=r"(r[1]), "=r"(r[2]), "=r"(r[3]) : "r"(addr));
}
__device__ __forceinline__ void ldsm_x4_t(uint32_t r[4], uint32_t addr) {
    asm volatile("ldmatrix.sync.aligned.m8n8.x4.trans.shared.b16 {%0,%1,%2,%3}, [%4];"
                 : "=r"(r[0]), "=r"(r[1]), "=r"(r[2]), "=r"(r[3]) : "r"(addr));
}
__device__ __forceinline__ void mma16816(float c[4], const uint32_t a[4], const uint32_t b[2]) {
    asm("mma.sync.aligned.m16n8k16.row.col.f32.bf16.bf16.f32 "
        "{%0,%1,%2,%3}, {%4,%5,%6,%7}, {%8,%9}, {%0,%1,%2,%3};"
        : "+f"(c[0]), "+f"(c[1]), "+f"(c[2]), "+f"(c[3])
        : "r"(a[0]), "r"(a[1]), "r"(a[2]), "r"(a[3]), "r"(b[0]), "r"(b[1]));
}
__device__ __forceinline__ void cpa16(uint32_t dst, const void* src) {
    asm volatile("cp.async.cg.shared.global [%0], [%1], 16;" :: "r"(dst), "l"(src));
}
__device__ __forceinline__ uint32_t packbf(float lo, float hi) {
    uint32_t r;
    asm("cvt.rn.bf16x2.f32 %0, %1, %2;" : "=r"(r) : "f"(hi), "f"(lo));
    return r;
}
__device__ __forceinline__ void split2(float2 v, __nv_bfloat162& h, __nv_bfloat162& l) {
    h.x = __float2bfloat16(v.x); h.y = __float2bfloat16(v.y);
    l.x = __float2bfloat16(v.x - __bfloat162float(h.x));
    l.y = __float2bfloat16(v.y - __bfloat162float(h.y));
}

// ---------------------------------------------------------------------------
// Kernel: fp32 -> (bf16 hi, bf16 lo) split
// ---------------------------------------------------------------------------
__global__ __launch_bounds__(256)
void split_bf16(const float* __restrict__ X, __nv_bfloat16* __restrict__ H,
                __nv_bfloat16* __restrict__ Lo, int n2)
{
    int i = blockIdx.x * blockDim.x + threadIdx.x;
    if (i >= n2) return;
    float2 x = ((const float2*)X)[i];
    __nv_bfloat162 hv, lv;
    split2(x, hv, lv);
    ((__nv_bfloat162*)H)[i]  = hv;
    ((__nv_bfloat162*)Lo)[i] = lv;
}

// ---------------------------------------------------------------------------
// Kernel: RoPE cos/sin table
// ---------------------------------------------------------------------------
__global__ __launch_bounds__(256)
void rope_table(float2* __restrict__ T)
{
    int idx = blockIdx.x * blockDim.x + threadIdx.x;
    if (idx >= Ll * 32) return;
    const int l = idx >> 5, j = idx & 31;
    const float inv_freq = __expf(-(float)j * (9.210340371976184f / 32.0f));
    float s, c;
    sincosf((float)l * inv_freq, &s, &c);
    T[idx] = make_float2(c, s);
}

// ---------------------------------------------------------------------------
// mma.sync bf16-split GEMM with software-pipelined B fragments.
// EPI=0: fp32 C+bias. EPI=1: fused bias+RoPE+split scatter to q/k/v.
// ---------------------------------------------------------------------------
#define PADW 40
#define KC   32
#define TILE_BYTES (128 * PADW * 2)
#define STAGE_BYTES (4 * TILE_BYTES)
#define GSMEM (2 * STAGE_BYTES)

template<int EPI>
__global__ __launch_bounds__(256, 2)
void gemm_mma_split(const __nv_bfloat16* __restrict__ Ah, const __nv_bfloat16* __restrict__ Al,
                    const __nv_bfloat16* __restrict__ Bh, const __nv_bfloat16* __restrict__ Bl,
                    const float* __restrict__ bias, float* __restrict__ C,
                    __nv_bfloat16* __restrict__ Qh, __nv_bfloat16* __restrict__ Ql,
                    __nv_bfloat16* __restrict__ Kh, __nv_bfloat16* __restrict__ Kl,
                    __nv_bfloat16* __restrict__ Vh, __nv_bfloat16* __restrict__ Vl,
                    const float2* __restrict__ Rt,
                    int M, int N, int K)
{
    extern __shared__ char dsm[];
    const uint32_t sbase = smem_u32(dsm);

    const int tid  = threadIdx.x;
    const int lane = tid & 31;
    const int wid  = tid >> 5;
    const int wm   = wid & 3;
    const int wn   = wid >> 2;
    const int m0   = blockIdx.y * 128;
    const int n0   = blockIdx.x * 128;

    float c[2][8][4];
#pragma unroll
    for (int i = 0; i < 2; i++)
#pragma unroll
        for (int j = 0; j < 8; j++)
#pragma unroll
            for (int q = 0; q < 4; q++) c[i][j][q] = 0.f;

    const int lr  = tid >> 2;
    const int lcc = (tid & 3) * 8;
    const __nv_bfloat16* srcs[4] = {
        Ah + (size_t)(m0 + lr) * K + lcc,  Al + (size_t)(m0 + lr) * K + lcc,
        Bh + (size_t)(n0 + lr) * K + lcc,  Bl + (size_t)(n0 + lr) * K + lcc };
    const size_t rowskip = (size_t)64 * K;
    const uint32_t dst0 = sbase + (uint32_t)(lr * PADW + lcc) * 2;
    const uint32_t dst1 = dst0 + (uint32_t)(64 * PADW) * 2;

    const int arow = wm * 32 + (lane & 15);
    const int acol = (lane >> 4) * 8;
    const int brow = wn * 64 + ((lane >> 4) << 3) + (lane & 7);
    const int bcol = ((lane >> 3) & 1) * 8;
    const uint32_t aAh = sbase + 0 * TILE_BYTES + (uint32_t)(arow * PADW + acol) * 2;
    const uint32_t aAl = sbase + 1 * TILE_BYTES + (uint32_t)(arow * PADW + acol) * 2;
    const uint32_t aBh = sbase + 2 * TILE_BYTES + (uint32_t)(brow * PADW + bcol) * 2;
    const uint32_t aBl = sbase + 3 * TILE_BYTES + (uint32_t)(brow * PADW + bcol) * 2;

    const int nch = K / KC;

#pragma unroll
    for (int t = 0; t < 4; t++) {
        const uint32_t toff = t * TILE_BYTES;
        cpa16(dst0 + toff, srcs[t]);
        cpa16(dst1 + toff, srcs[t] + rowskip);
    }
    asm volatile("cp.async.commit_group;");

    for (int s = 0; s < nch; s++) {
        if (s + 1 < nch) {
            const uint32_t stoff = ((s + 1) & 1) * (uint32_t)STAGE_BYTES;
            const int koff = (s + 1) * KC;
#pragma unroll
            for (int t = 0; t < 4; t++) {
                const uint32_t toff = stoff + t * TILE_BYTES;
                cpa16(dst0 + toff, srcs[t] + koff);
                cpa16(dst1 + toff, srcs[t] + koff + rowskip);
            }
            asm volatile("cp.async.commit_group;");
            asm volatile("cp.async.wait_group 1;");
        } else {
            asm volatile("cp.async.wait_group 0;");
        }
        __syncthreads();

        const uint32_t stoff = (s & 1) * (uint32_t)STAGE_BYTES;
#pragma unroll
        for (int ks = 0; ks < 2; ks++) {
            const uint32_t kb = (uint32_t)(ks * 16 * 2);
            uint32_t ahf[2][4], alf[2][4];
#pragma unroll
            for (int mt = 0; mt < 2; mt++) {
                const uint32_t moff = stoff + (uint32_t)(mt * 16 * PADW * 2) + kb;
                ldsm_x4(ahf[mt], aAh + moff);
                ldsm_x4(alf[mt], aAl + moff);
            }
            // software-pipelined B fragments: prefetch nt+1 before MMAs of nt
            uint32_t bhf[2][4], blf[2][4];
            ldsm_x4(bhf[0], aBh + stoff + kb);
            ldsm_x4(blf[0], aBl + stoff + kb);
#pragma unroll
            for (int nt = 0; nt < 4; nt++) {
                const int cur = nt & 1;
                if (nt < 3) {
                    const uint32_t noff = stoff + (uint32_t)((nt + 1) * 16 * PADW * 2) + kb;
                    ldsm_x4(bhf[cur ^ 1], aBh + noff);
                    ldsm_x4(blf[cur ^ 1], aBl + noff);
                }
                mma16816(c[0][nt * 2 + 0], ahf[0], &bhf[cur][0]);
                mma16816(c[0][nt * 2 + 1], ahf[0], &bhf[cur][2]);
                mma16816(c[1][nt * 2 + 0], ahf[1], &bhf[cur][0]);
                mma16816(c[1][nt * 2 + 1], ahf[1], &bhf[cur][2]);
                mma16816(c[0][nt * 2 + 0], ahf[0], &blf[cur][0]);
                mma16816(c[0][nt * 2 + 1], ahf[0], &blf[cur][2]);
                mma16816(c[1][nt * 2 + 0], ahf[1], &blf[cur][0]);
                mma16816(c[1][nt * 2 + 1], ahf[1], &blf[cur][2]);
                mma16816(c[0][nt * 2 + 0], alf[0], &bhf[cur][0]);
                mma16816(c[0][nt * 2 + 1], alf[0], &bhf[cur][2]);
                mma16816(c[1][nt * 2 + 0], alf[1], &bhf[cur][0]);
                mma16816(c[1][nt * 2 + 1], alf[1], &bhf[cur][2]);
            }
        }
        __syncthreads();
    }

#pragma unroll
    for (int mt = 0; mt < 2; mt++) {
        const int mrow = m0 + wm * 32 + mt * 16 + (lane >> 2);
#pragma unroll
        for (int n8 = 0; n8 < 8; n8++) {
            const int ncol = n0 + wn * 64 + n8 * 8 + 2 * (lane & 3);
            float2 bb = *(const float2*)(bias + ncol);
            if (EPI == 0) {
                float2 o0, o1;
                o0.x = c[mt][n8][0] + bb.x; o0.y = c[mt][n8][1] + bb.y;
                o1.x = c[mt][n8][2] + bb.x; o1.y = c[mt][n8][3] + bb.y;
                *(float2*)&C[(size_t)mrow * N + ncol]       = o0;
                *(float2*)&C[(size_t)(mrow + 8) * N + ncol] = o1;
            } else {
                const int sec  = ncol >> 10;        // 0=q, 1=k, 2=v
                const int hcol = ncol & 1023;
                const int hh   = hcol >> 6;
                const int j    = (hcol & 63) >> 1;
                __nv_bfloat16* Hd = (sec == 0) ? Qh : (sec == 1) ? Kh : Vh;
                __nv_bfloat16* Ld = (sec == 0) ? Ql : (sec == 1) ? Kl : Vl;
#pragma unroll
                for (int r = 0; r < 2; r++) {
                    const int mr = mrow + r * 8;
                    const int l  = mr & (Ll - 1);
                    const int b  = mr >> 11;
                    float2 v;
                    v.x = c[mt][n8][2 * r]     + bb.x;
                    v.y = c[mt][n8][2 * r + 1] + bb.y;
                    if (sec < 2) {
                        const float2 cs = Rt[l * 32 + j];
                        float nx = v.x * cs.x - v.y * cs.y;
                        float ny = v.x * cs.y + v.y * cs.x;
                        if (sec == 0) { nx *= 0.125f; ny *= 0.125f; }
                        v.x = nx; v.y = ny;
                    }
                    __nv_bfloat162 hv, lv;
                    split2(v, hv, lv);
                    const size_t base = ((size_t)(b * Hh + hh) * Ll + l) * 32 + j;
                    ((__nv_bfloat162*)Hd)[base] = hv;
                    ((__nv_bfloat162*)Ld)[base] = lv;
                }
            }
        }
    }
}

// ---------------------------------------------------------------------------
// Flash attention with mma.sync bf16-split (inverted mask), pipelined frags.
// ---------------------------------------------------------------------------
#define QSTR 72
#define ATILE_B (64 * QSTR * 2)
#define AKV_B   (4 * ATILE_B)
#define ASMEM (2 * ATILE_B + 2 * AKV_B)

__global__ __launch_bounds__(128, 2)
void attn_mma(const __nv_bfloat16* __restrict__ Qh, const __nv_bfloat16* __restrict__ Ql,
              const __nv_bfloat16* __restrict__ Kh, const __nv_bfloat16* __restrict__ Kl,
              const __nv_bfloat16* __restrict__ Vh, const __nv_bfloat16* __restrict__ Vl,
              __nv_bfloat16* __restrict__ OAh, __nv_bfloat16* __restrict__ OAl)
{
    extern __shared__ char sm[];
    const uint32_t sb = smem_u32(sm);
    const int bh  = blockIdx.y;
    const int qt  = blockIdx.x;
    const int q0  = qt * 64;
    const int tid = threadIdx.x;
    const int lane = tid & 31;
    const int wid  = tid >> 5;

    const uint32_t oQ  = 0;
    const uint32_t oKV = 2 * ATILE_B;

    {
        const __nv_bfloat16* qsrc[2] = { Qh + ((size_t)bh * Ll + q0) * 64,
                                         Ql + ((size_t)bh * Ll + q0) * 64 };
#pragma unroll
        for (int i = 0; i < 8; i++) {
            int idx = i * 128 + tid;
            int t = idx >> 9, r = (idx >> 3) & 63, cc = idx & 7;
            cpa16(sb + oQ + t * ATILE_B + (uint32_t)(r * QSTR + cc * 8) * 2,
                  qsrc[t] + (size_t)r * 64 + cc * 8);
        }
        asm volatile("cp.async.commit_group;");
    }

    const int jstart = (qt < 24) ? qt : 24;
    const int nj = 32 - jstart;

    const __nv_bfloat16* kvsrc[4] = {
        Kh + (size_t)bh * Ll * 64, Kl + (size_t)bh * Ll * 64,
        Vh + (size_t)bh * Ll * 64, Vl + (size_t)bh * Ll * 64 };

    {
        const int kt = jstart * 64;
#pragma unroll
        for (int i = 0; i < 16; i++) {
            int idx = i * 128 + tid;
            int t = idx >> 9, r = (idx >> 3) & 63, cc = idx & 7;
            cpa16(sb + oKV + t * ATILE_B + (uint32_t)(r * QSTR + cc * 8) * 2,
                  kvsrc[t] + (size_t)(kt + r) * 64 + cc * 8);
        }
        asm volatile("cp.async.commit_group;");
    }

    asm volatile("cp.async.wait_group 1;");
    __syncthreads();

    uint32_t fqh[4][4], fql[4][4];
    {
        const uint32_t qaddr = sb + oQ +
            (uint32_t)((wid * 16 + (lane & 15)) * QSTR + (lane >> 4) * 8) * 2;
#pragma unroll
        for (int c = 0; c < 4; c++) {
            ldsm_x4(fqh[c], qaddr + c * 32);
            ldsm_x4(fql[c], qaddr + ATILE_B + c * 32);
        }
    }

    float m1 = -5e29f, m2 = -5e29f, l1 = 0.f, l2 = 0.f;
    float acc[8][4];
#pragma unroll
    for (int j = 0; j < 8; j++)
#pragma unroll
        for (int d = 0; d < 4; d++) acc[j][d] = 0.f;

    const int r1 = q0 + wid * 16 + (lane >> 2);

    const uint32_t kaddr0 = (uint32_t)((((lane >> 4) << 3) + (lane & 7)) * QSTR
                                        + ((lane >> 3) & 1) * 8) * 2;
    const uint32_t vaddr0 = (uint32_t)((lane & 15) * QSTR + (lane >> 4) * 8) * 2;

    for (int tix = 0; tix < nj; tix++) {
        const int kt = (jstart + tix) * 64;
        const int st = tix & 1;

        if (tix + 1 < nj) {
            const int ktn = kt + 64;
            const uint32_t soff = oKV + (st ^ 1) * AKV_B;
#pragma unroll
            for (int i = 0; i < 16; i++) {
                int idx = i * 128 + tid;
                int t = idx >> 9, r = (idx >> 3) & 63, cc = idx & 7;
                cpa16(sb + soff + t * ATILE_B + (uint32_t)(r * QSTR + cc * 8) * 2,
                      kvsrc[t] + (size_t)(ktn + r) * 64 + cc * 8);
            }
            asm volatile("cp.async.commit_group;");
            asm volatile("cp.async.wait_group 1;");
        } else {
            asm volatile("cp.async.wait_group 0;");
        }
        __syncthreads();

        const uint32_t sKh = sb + oKV + st * AKV_B;
        const uint32_t sKl = sKh + ATILE_B;
        const uint32_t sVh = sKh + 2 * ATILE_B;
        const uint32_t sVl = sKh + 3 * ATILE_B;

        // ---- S = Q K^T, pipelined: (c, nt) flattened, prefetch next K frag ----
        float s[8][4];
#pragma unroll
        for (int jb = 0; jb < 8; jb++)
#pragma unroll
            for (int d = 0; d < 4; d++) s[jb][d] = 0.f;

        {
            uint32_t khf[2][4], klf[2][4];
            ldsm_x4(khf[0], sKh + kaddr0);
            ldsm_x4(klf[0], sKl + kaddr0);
#pragma unroll
            for (int ix = 0; ix < 16; ix++) {
                const int c  = ix >> 2;          // k-chunk
                const int nt = ix & 3;           // key subtile
                const int cur = ix & 1;
                if (ix < 15) {
                    const int cn  = (ix + 1) >> 2;
                    const int ntn = (ix + 1) & 3;
                    const uint32_t noff = (uint32_t)(ntn * 16 * QSTR * 2) + cn * 32;
                    ldsm_x4(khf[cur ^ 1], sKh + kaddr0 + noff);
                    ldsm_x4(klf[cur ^ 1], sKl + kaddr0 + noff);
                }
                mma16816(s[nt * 2 + 0], fqh[c], &khf[cur][0]);
                mma16816(s[nt * 2 + 1], fqh[c], &khf[cur][2]);
                mma16816(s[nt * 2 + 0], fqh[c], &klf[cur][0]);
                mma16816(s[nt * 2 + 1], fqh[c], &klf[cur][2]);
                mma16816(s[nt * 2 + 0], fql[c], &khf[cur][0]);
                mma16816(s[nt * 2 + 1], fql[c], &khf[cur][2]);
            }
        }

        if (kt == q0 && kt < PAD) {
            const int cbase = kt + 2 * (lane & 3);
#pragma unroll
            for (int jb = 0; jb < 8; jb++) {
                const int c0 = cbase + jb * 8;
                s[jb][0] = (c0     > r1) ? s[jb][0] : -1e30f;
                s[jb][1] = (c0 + 1 > r1) ? s[jb][1] : -1e30f;
                s[jb][2] = (c0     > r1 + 8) ? s[jb][2] : -1e30f;
                s[jb][3] = (c0 + 1 > r1 + 8) ? s[jb][3] : -1e30f;
            }
        }

        float t1 = -1e30f, t2 = -1e30f;
#pragma unroll
        for (int jb = 0; jb < 8; jb++) {
            t1 = fmaxf(t1, fmaxf(s[jb][0], s[jb][1]));
            t2 = fmaxf(t2, fmaxf(s[jb][2], s[jb][3]));
        }
        t1 = fmaxf(t1, __shfl_xor_sync(0xffffffffu, t1, 1));
        t1 = fmaxf(t1, __shfl_xor_sync(0xffffffffu, t1, 2));
        t2 = fmaxf(t2, __shfl_xor_sync(0xffffffffu, t2, 1));
        t2 = fmaxf(t2, __shfl_xor_sync(0xffffffffu, t2, 2));

        const float mn1 = fmaxf(m1, t1);
        const float mn2 = fmaxf(m2, t2);
        const float a1 = __expf(m1 - mn1);
        const float a2 = __expf(m2 - mn2);
        m1 = mn1; m2 = mn2;

        float sum1 = 0.f, sum2 = 0.f;
#pragma unroll
        for (int jb = 0; jb < 8; jb++) {
            s[jb][0] = __expf(s[jb][0] - mn1);
            s[jb][1] = __expf(s[jb][1] - mn1);
            s[jb][2] = __expf(s[jb][2] - mn2);
            s[jb][3] = __expf(s[jb][3] - mn2);
            sum1 += s[jb][0] + s[jb][1];
            sum2 += s[jb][2] + s[jb][3];
        }
        sum1 += __shfl_xor_sync(0xffffffffu, sum1, 1);
        sum1 += __shfl_xor_sync(0xffffffffu, sum1, 2);
        sum2 += __shfl_xor_sync(0xffffffffu, sum2, 1);
        sum2 += __shfl_xor_sync(0xffffffffu, sum2, 2);
        l1 = l1 * a1 + sum1;
        l2 = l2 * a2 + sum2;

#pragma unroll
        for (int jb = 0; jb < 8; jb++) {
            acc[jb][0] *= a1; acc[jb][1] *= a1;
            acc[jb][2] *= a2; acc[jb][3] *= a2;
        }

        uint32_t fph[4][4], fpl[4][4];
#pragma unroll
        for (int c = 0; c < 4; c++) {
            const float* p0 = s[2 * c];
            const float* p1 = s[2 * c + 1];
            fph[c][0] = packbf(p0[0], p0[1]);
            fph[c][1] = packbf(p0[2], p0[3]);
            fph[c][2] = packbf(p1[0], p1[1]);
            fph[c][3] = packbf(p1[2], p1[3]);
#pragma unroll
            for (int r = 0; r < 4; r++) {
                __nv_bfloat162 hb = *(__nv_bfloat162*)&fph[c][r];
                const float* src = (r < 2) ? p0 : p1;
                const int o = (r & 1) * 2;
                fpl[c][r] = packbf(src[o] - __bfloat162float(hb.x),
                                   src[o + 1] - __bfloat162float(hb.y));
            }
        }

        // ---- O += P V, pipelined: (c, ng) flattened, prefetch next V frag ----
        {
            uint32_t vhf[2][4], vlf[2][4];
            ldsm_x4_t(vhf[0], sVh + vaddr0);
            ldsm_x4_t(vlf[0], sVl + vaddr0);
#pragma unroll
            for (int ix = 0; ix < 16; ix++) {
                const int c  = ix >> 2;
                const int ng = ix & 3;
                const int cur = ix & 1;
                if (ix < 15) {
                    const int cn  = (ix + 1) >> 2;
                    const int ngn = (ix + 1) & 3;
                    const uint32_t aoff = (uint32_t)(cn * 16 * QSTR * 2) + vaddr0
                                        + (uint32_t)(ngn * 16 * 2);
                    ldsm_x4_t(vhf[cur ^ 1], sVh + aoff);
                    ldsm_x4_t(vlf[cur ^ 1], sVl + aoff);
                }
                mma16816(acc[ng * 2 + 0], fph[c], &vhf[cur][0]);
                mma16816(acc[ng * 2 + 1], fph[c], &vhf[cur][2]);
                mma16816(acc[ng * 2 + 0], fph[c], &vlf[cur][0]);
                mma16816(acc[ng * 2 + 1], fph[c], &vlf[cur][2]);
                mma16816(acc[ng * 2 + 0], fpl[c], &vhf[cur][0]);
                mma16816(acc[ng * 2 + 1], fpl[c], &vhf[cur][2]);
            }
        }
        __syncthreads();
    }

    // ---- epilogue: split to bf16 hi/lo, write out-proj A buffers ----
    const int b = bh >> 4;
    const int hh = bh & 15;
    const float inv1 = 1.f / l1;
    const float inv2 = 1.f / l2;
    const size_t row1 = (size_t)(b * Ll) + r1;
    const int col0 = hh * 64 + 2 * (lane & 3);
    __nv_bfloat162* H1 = (__nv_bfloat162*)OAh + row1 * (Dm / 2) + (col0 >> 1);
    __nv_bfloat162* L1 = (__nv_bfloat162*)OAl + row1 * (Dm / 2) + (col0 >> 1);
    __nv_bfloat162* H2 = H1 + 8 * (Dm / 2);
    __nv_bfloat162* L2 = L1 + 8 * (Dm / 2);
#pragma unroll
    for (int jb = 0; jb < 8; jb++) {
        float2 w1, w2;
        w1.x = acc[jb][0] * inv1; w1.y = acc[jb][1] * inv1;
        w2.x = acc[jb][2] * inv2; w2.y = acc[jb][3] * inv2;
        __nv_bfloat162 hv, lv;
        split2(w1, hv, lv); H1[jb * 4] = hv; L1[jb * 4] = lv;
        split2(w2, hv, lv); H2[jb * 4] = hv; L2[jb * 4] = lv;
    }
}

// ---------------------------------------------------------------------------
// Launch
// ---------------------------------------------------------------------------
extern "C" void kernel_launch(void* const* d_in, const int* in_sizes, int n_in,
                              void* d_out, int out_size)
{
    const float* x    = (const float*)d_in[0];
    const float* Wqkv = (const float*)d_in[2];
    const float* bqkv = (const float*)d_in[3];
    const float* Wout = (const float*)d_in[4];
    const float* bout = (const float*)d_in[5];
    float* out = (float*)d_out;

    __nv_bfloat16 *ah, *al, *bhp, *blp, *qh, *ql, *kh, *kl, *vh, *vl;
    float2* rt;
    cudaGetSymbolAddress((void**)&ah,   g_ah);
    cudaGetSymbolAddress((void**)&al,   g_al);
    cudaGetSymbolAddress((void**)&bhp,  g_bh);
    cudaGetSymbolAddress((void**)&blp,  g_bl);
    cudaGetSymbolAddress((void**)&qh,   g_qh);
    cudaGetSymbolAddress((void**)&ql,   g_ql);
    cudaGetSymbolAddress((void**)&kh,   g_kh);
    cudaGetSymbolAddress((void**)&kl,   g_kl);
    cudaGetSymbolAddress((void**)&vh,   g_vh);
    cudaGetSymbolAddress((void**)&vl,   g_vl);
    cudaGetSymbolAddress((void**)&rt,   g_rope);

    cudaFuncSetAttribute(gemm_mma_split<0>, cudaFuncAttributeMaxDynamicSharedMemorySize, GSMEM);
    cudaFuncSetAttribute(gemm_mma_split<1>, cudaFuncAttributeMaxDynamicSharedMemorySize, GSMEM);
    cudaFuncSetAttribute(attn_mma, cudaFuncAttributeMaxDynamicSharedMemorySize, ASMEM);

    // 1) rope table + split x and Wqkv
    {
        rope_table<<<(Ll * 32 + 255) / 256, 256>>>(rt);
        int n2 = (Mrows * Dm) / 2;
        split_bf16<<<(n2 + 255) / 256, 256>>>(x, ah, al, n2);
        n2 = (QKVN * Dm) / 2;
        split_bf16<<<(n2 + 255) / 256, 256>>>(Wqkv, bhp, blp, n2);
    }
    // 2) QKV projection + bias + RoPE + split scatter
    {
        dim3 grid(QKVN / 128, Mrows / 128);
        gemm_mma_split<1><<<grid, 256, GSMEM>>>(ah, al, bhp, blp, bqkv, nullptr,
                                                qh, ql, kh, kl, vh, vl, rt,
                                                Mrows, QKVN, Dm);
    }
    // 3) attention
    {
        dim3 grid(Ll / 64, Bb * Hh);
        attn_mma<<<grid, 128, ASMEM>>>(qh, ql, kh, kl, vh, vl, ah, al);
    }
    // 4) split Wout
    {
        int n2 = (Dm * Dm) / 2;
        split_bf16<<<(n2 + 255) / 256, 256>>>(Wout, bhp, blp, n2);
    }
    // 5) output projection + bias
    {
        dim3 grid(Dm / 128, Mrows / 128);
        gemm_mma_split<0><<<grid, 256, GSMEM>>>(ah, al, bhp, blp, bout, out,
                                                nullptr, nullptr, nullptr, nullptr,
                                                nullptr, nullptr, nullptr,
                                                Mrows, Dm, Dm);
    }
}

// round 12
// speedup vs baseline: 1.2136x; 1.2136x over previous
#include <cuda_runtime.h>
#include <cuda_bf16.h>
#include <cuda_fp16.h>
#include <cstdint>
#include <math.h>

// Problem constants (fixed by the dataset)
#define Bb   2
#define Ll   2048
#define Dm   1024
#define Hh   16
#define DhD  64
#define PAD  1536
#define Mrows (Bb * Ll)          // 4096
#define QKVN  (3 * Dm)           // 3072

// ---------------------------------------------------------------------------
// Scratch (device globals; no runtime allocation allowed)
// ---------------------------------------------------------------------------
// fp16 A operand (x, then attn-out), 2-term split; fp16 B operand (weights)
__device__ __half g_ah[(size_t)Mrows * Dm];
__device__ __half g_al[(size_t)Mrows * Dm];
__device__ __half g_bw[(size_t)QKVN * Dm];
// bf16 hi/lo q/k/v in [B*H][L][64] layout (q pre-scaled by 1/8) for attention
#define QKVSZ ((size_t)Bb * Hh * Ll * DhD)
__device__ __nv_bfloat16 g_qh[QKVSZ], g_ql[QKVSZ];
__device__ __nv_bfloat16 g_kh[QKVSZ], g_kl[QKVSZ];
__device__ __nv_bfloat16 g_vh[QKVSZ], g_vl[QKVSZ];
__device__ float2 g_rope[Ll * 32];

// ---------------------------------------------------------------------------
// mma.sync helpers
// ---------------------------------------------------------------------------
__device__ __forceinline__ uint32_t smem_u32(const void* p) {
    uint32_t a;
    asm("{ .reg .u64 t; cvta.to.shared.u64 t, %1; cvt.u32.u64 %0, t; }" : "=r"(a) : "l"(p));
    return a;
}
__device__ __forceinline__ void ldsm_x4(uint32_t r[4], uint32_t addr) {
    asm volatile("ldmatrix.sync.aligned.m8n8.x4.shared.b16 {%0,%1,%2,%3}, [%4];"
                 : "=r"(r[0]), "=r"(r[1]), "=r"(r[2]), "=r"(r[3]) : "r"(addr));
}
__device__ __forceinline__ void ldsm_x4_t(uint32_t r[4], uint32_t addr) {
    asm volatile("ldmatrix.sync.aligned.m8n8.x4.trans.shared.b16 {%0,%1,%2,%3}, [%4];"
                 : "=r"(r[0]), "=r"(r[1]), "=r"(r[2]), "=r"(r[3]) : "r"(addr));
}
// bf16 mma (attention)
__device__ __forceinline__ void mma16816(float c[4], const uint32_t a[4], const uint32_t b[2]) {
    asm("mma.sync.aligned.m16n8k16.row.col.f32.bf16.bf16.f32 "
        "{%0,%1,%2,%3}, {%4,%5,%6,%7}, {%8,%9}, {%0,%1,%2,%3};"
        : "+f"(c[0]), "+f"(c[1]), "+f"(c[2]), "+f"(c[3])
        : "r"(a[0]), "r"(a[1]), "r"(a[2]), "r"(a[3]), "r"(b[0]), "r"(b[1]));
}
// fp16 mma (projection GEMMs)
__device__ __forceinline__ void mma16816h(float c[4], const uint32_t a[4], const uint32_t b[2]) {
    asm("mma.sync.aligned.m16n8k16.row.col.f32.f16.f16.f32 "
        "{%0,%1,%2,%3}, {%4,%5,%6,%7}, {%8,%9}, {%0,%1,%2,%3};"
        : "+f"(c[0]), "+f"(c[1]), "+f"(c[2]), "+f"(c[3])
        : "r"(a[0]), "r"(a[1]), "r"(a[2]), "r"(a[3]), "r"(b[0]), "r"(b[1]));
}
__device__ __forceinline__ void cpa16(uint32_t dst, const void* src) {
    asm volatile("cp.async.cg.shared.global [%0], [%1], 16;" :: "r"(dst), "l"(src));
}
__device__ __forceinline__ uint32_t packbf(float lo, float hi) {
    uint32_t r;
    asm("cvt.rn.bf16x2.f32 %0, %1, %2;" : "=r"(r) : "f"(hi), "f"(lo));
    return r;
}
__device__ __forceinline__ void split2(float2 v, __nv_bfloat162& h, __nv_bfloat162& l) {
    h.x = __float2bfloat16(v.x); h.y = __float2bfloat16(v.y);
    l.x = __float2bfloat16(v.x - __bfloat162float(h.x));
    l.y = __float2bfloat16(v.y - __bfloat162float(h.y));
}
__device__ __forceinline__ void split2h(float2 v, __half2& h, __half2& l) {
    h = __floats2half2_rn(v.x, v.y);
    float2 hf = __half22float2(h);
    l = __floats2half2_rn(v.x - hf.x, v.y - hf.y);
}

// ---------------------------------------------------------------------------
// Kernel: fp32 -> (fp16 hi, fp16 lo) split, 2 elements/thread
// ---------------------------------------------------------------------------
__global__ __launch_bounds__(256)
void split_fp16(const float* __restrict__ X, __half* __restrict__ H,
                __half* __restrict__ Lo, int n2)
{
    int i = blockIdx.x * blockDim.x + threadIdx.x;
    if (i >= n2) return;
    float2 x = ((const float2*)X)[i];
    __half2 hv, lv;
    split2h(x, hv, lv);
    ((__half2*)H)[i]  = hv;
    ((__half2*)Lo)[i] = lv;
}

// ---------------------------------------------------------------------------
// Kernel: fp32 -> fp16 convert (weights)
// ---------------------------------------------------------------------------
__global__ __launch_bounds__(256)
void cvt_fp16(const float* __restrict__ X, __half* __restrict__ H, int n2)
{
    int i = blockIdx.x * blockDim.x + threadIdx.x;
    if (i >= n2) return;
    float2 x = ((const float2*)X)[i];
    ((__half2*)H)[i] = __floats2half2_rn(x.x, x.y);
}

// ---------------------------------------------------------------------------
// Kernel: RoPE cos/sin table
// ---------------------------------------------------------------------------
__global__ __launch_bounds__(256)
void rope_table(float2* __restrict__ T)
{
    int idx = blockIdx.x * blockDim.x + threadIdx.x;
    if (idx >= Ll * 32) return;
    const int l = idx >> 5, j = idx & 31;
    const float inv_freq = __expf(-(float)j * (9.210340371976184f / 32.0f));
    float s, c;
    sincosf((float)l * inv_freq, &s, &c);
    T[idx] = make_float2(c, s);
}

// ---------------------------------------------------------------------------
// fp16 asymmetric-split GEMM: C[M,N] = (Ah+Al)[M,K] * B[N,K]^T + bias
// 2 MMA passes (A hi, A lo) x single fp16 B. 3 smem tiles/stage.
// EPI=0: fp32 C+bias. EPI=1: fused bias+RoPE+bf16-split scatter to q/k/v.
// ---------------------------------------------------------------------------
#define PADW 40
#define KC   32
#define TILE_BYTES (128 * PADW * 2)
#define STAGE_BYTES (3 * TILE_BYTES)
#define GSMEM (2 * STAGE_BYTES)

template<int EPI>
__global__ __launch_bounds__(256, 2)
void gemm_mma_split(const __half* __restrict__ Ah, const __half* __restrict__ Al,
                    const __half* __restrict__ Bw,
                    const float* __restrict__ bias, float* __restrict__ C,
                    __nv_bfloat16* __restrict__ Qh, __nv_bfloat16* __restrict__ Ql,
                    __nv_bfloat16* __restrict__ Kh, __nv_bfloat16* __restrict__ Kl,
                    __nv_bfloat16* __restrict__ Vh, __nv_bfloat16* __restrict__ Vl,
                    const float2* __restrict__ Rt,
                    int M, int N, int K)
{
    extern __shared__ char dsm[];
    const uint32_t sbase = smem_u32(dsm);

    const int tid  = threadIdx.x;
    const int lane = tid & 31;
    const int wid  = tid >> 5;
    const int wm   = wid & 3;
    const int wn   = wid >> 2;
    const int m0   = blockIdx.y * 128;
    const int n0   = blockIdx.x * 128;

    float c[2][8][4];
#pragma unroll
    for (int i = 0; i < 2; i++)
#pragma unroll
        for (int j = 0; j < 8; j++)
#pragma unroll
            for (int q = 0; q < 4; q++) c[i][j][q] = 0.f;

    const int lr  = tid >> 2;
    const int lcc = (tid & 3) * 8;
    const __half* srcs[3] = {
        Ah + (size_t)(m0 + lr) * K + lcc,
        Al + (size_t)(m0 + lr) * K + lcc,
        Bw + (size_t)(n0 + lr) * K + lcc };
    const size_t rowskip = (size_t)64 * K;
    const uint32_t dst0 = sbase + (uint32_t)(lr * PADW + lcc) * 2;
    const uint32_t dst1 = dst0 + (uint32_t)(64 * PADW) * 2;

    const int arow = wm * 32 + (lane & 15);
    const int acol = (lane >> 4) * 8;
    const int brow = wn * 64 + ((lane >> 4) << 3) + (lane & 7);
    const int bcol = ((lane >> 3) & 1) * 8;
    const uint32_t aAh = sbase + 0 * TILE_BYTES + (uint32_t)(arow * PADW + acol) * 2;
    const uint32_t aAl = sbase + 1 * TILE_BYTES + (uint32_t)(arow * PADW + acol) * 2;
    const uint32_t aBw = sbase + 2 * TILE_BYTES + (uint32_t)(brow * PADW + bcol) * 2;

    const int nch = K / KC;

#pragma unroll
    for (int t = 0; t < 3; t++) {
        const uint32_t toff = t * TILE_BYTES;
        cpa16(dst0 + toff, srcs[t]);
        cpa16(dst1 + toff, srcs[t] + rowskip);
    }
    asm volatile("cp.async.commit_group;");

    for (int s = 0; s < nch; s++) {
        if (s + 1 < nch) {
            const uint32_t stoff = ((s + 1) & 1) * (uint32_t)STAGE_BYTES;
            const int koff = (s + 1) * KC;
#pragma unroll
            for (int t = 0; t < 3; t++) {
                const uint32_t toff = stoff + t * TILE_BYTES;
                cpa16(dst0 + toff, srcs[t] + koff);
                cpa16(dst1 + toff, srcs[t] + koff + rowskip);
            }
            asm volatile("cp.async.commit_group;");
            asm volatile("cp.async.wait_group 1;");
        } else {
            asm volatile("cp.async.wait_group 0;");
        }
        __syncthreads();

        const uint32_t stoff = (s & 1) * (uint32_t)STAGE_BYTES;
#pragma unroll
        for (int ks = 0; ks < 2; ks++) {
            const uint32_t kb = (uint32_t)(ks * 16 * 2);
            uint32_t ahf[2][4], alf[2][4];
#pragma unroll
            for (int mt = 0; mt < 2; mt++) {
                const uint32_t moff = stoff + (uint32_t)(mt * 16 * PADW * 2) + kb;
                ldsm_x4(ahf[mt], aAh + moff);
                ldsm_x4(alf[mt], aAl + moff);
            }
            // pipelined B fragments
            uint32_t bwf[2][4];
            ldsm_x4(bwf[0], aBw + stoff + kb);
#pragma unroll
            for (int nt = 0; nt < 4; nt++) {
                const int cur = nt & 1;
                if (nt < 3) {
                    const uint32_t noff = stoff + (uint32_t)((nt + 1) * 16 * PADW * 2) + kb;
                    ldsm_x4(bwf[cur ^ 1], aBw + noff);
                }
                mma16816h(c[0][nt * 2 + 0], ahf[0], &bwf[cur][0]);
                mma16816h(c[0][nt * 2 + 1], ahf[0], &bwf[cur][2]);
                mma16816h(c[1][nt * 2 + 0], ahf[1], &bwf[cur][0]);
                mma16816h(c[1][nt * 2 + 1], ahf[1], &bwf[cur][2]);
                mma16816h(c[0][nt * 2 + 0], alf[0], &bwf[cur][0]);
                mma16816h(c[0][nt * 2 + 1], alf[0], &bwf[cur][2]);
                mma16816h(c[1][nt * 2 + 0], alf[1], &bwf[cur][0]);
                mma16816h(c[1][nt * 2 + 1], alf[1], &bwf[cur][2]);
            }
        }
        __syncthreads();
    }

#pragma unroll
    for (int mt = 0; mt < 2; mt++) {
        const int mrow = m0 + wm * 32 + mt * 16 + (lane >> 2);
#pragma unroll
        for (int n8 = 0; n8 < 8; n8++) {
            const int ncol = n0 + wn * 64 + n8 * 8 + 2 * (lane & 3);
            float2 bb = *(const float2*)(bias + ncol);
            if (EPI == 0) {
                float2 o0, o1;
                o0.x = c[mt][n8][0] + bb.x; o0.y = c[mt][n8][1] + bb.y;
                o1.x = c[mt][n8][2] + bb.x; o1.y = c[mt][n8][3] + bb.y;
                *(float2*)&C[(size_t)mrow * N + ncol]       = o0;
                *(float2*)&C[(size_t)(mrow + 8) * N + ncol] = o1;
            } else {
                const int sec  = ncol >> 10;        // 0=q, 1=k, 2=v
                const int hcol = ncol & 1023;
                const int hh   = hcol >> 6;
                const int j    = (hcol & 63) >> 1;
                __nv_bfloat16* Hd = (sec == 0) ? Qh : (sec == 1) ? Kh : Vh;
                __nv_bfloat16* Ld = (sec == 0) ? Ql : (sec == 1) ? Kl : Vl;
#pragma unroll
                for (int r = 0; r < 2; r++) {
                    const int mr = mrow + r * 8;
                    const int l  = mr & (Ll - 1);
                    const int b  = mr >> 11;
                    float2 v;
                    v.x = c[mt][n8][2 * r]     + bb.x;
                    v.y = c[mt][n8][2 * r + 1] + bb.y;
                    if (sec < 2) {
                        const float2 cs = Rt[l * 32 + j];
                        float nx = v.x * cs.x - v.y * cs.y;
                        float ny = v.x * cs.y + v.y * cs.x;
                        if (sec == 0) { nx *= 0.125f; ny *= 0.125f; }
                        v.x = nx; v.y = ny;
                    }
                    __nv_bfloat162 hv, lv;
                    split2(v, hv, lv);
                    const size_t base = ((size_t)(b * Hh + hh) * Ll + l) * 32 + j;
                    ((__nv_bfloat162*)Hd)[base] = hv;
                    ((__nv_bfloat162*)Ld)[base] = lv;
                }
            }
        }
    }
}

// ---------------------------------------------------------------------------
// Flash attention with mma.sync bf16-split (inverted mask).
// Epilogue writes fp16 hi/lo into out-proj A buffers.
// ---------------------------------------------------------------------------
#define QSTR 72
#define ATILE_B (64 * QSTR * 2)
#define AKV_B   (4 * ATILE_B)
#define ASMEM (2 * ATILE_B + 2 * AKV_B)

__global__ __launch_bounds__(128, 2)
void attn_mma(const __nv_bfloat16* __restrict__ Qh, const __nv_bfloat16* __restrict__ Ql,
              const __nv_bfloat16* __restrict__ Kh, const __nv_bfloat16* __restrict__ Kl,
              const __nv_bfloat16* __restrict__ Vh, const __nv_bfloat16* __restrict__ Vl,
              __half* __restrict__ OAh, __half* __restrict__ OAl)
{
    extern __shared__ char sm[];
    const uint32_t sb = smem_u32(sm);
    const int bh  = blockIdx.y;
    const int qt  = blockIdx.x;
    const int q0  = qt * 64;
    const int tid = threadIdx.x;
    const int lane = tid & 31;
    const int wid  = tid >> 5;

    const uint32_t oQ  = 0;
    const uint32_t oKV = 2 * ATILE_B;

    {
        const __nv_bfloat16* qsrc[2] = { Qh + ((size_t)bh * Ll + q0) * 64,
                                         Ql + ((size_t)bh * Ll + q0) * 64 };
#pragma unroll
        for (int i = 0; i < 8; i++) {
            int idx = i * 128 + tid;
            int t = idx >> 9, r = (idx >> 3) & 63, cc = idx & 7;
            cpa16(sb + oQ + t * ATILE_B + (uint32_t)(r * QSTR + cc * 8) * 2,
                  qsrc[t] + (size_t)r * 64 + cc * 8);
        }
        asm volatile("cp.async.commit_group;");
    }

    const int jstart = (qt < 24) ? qt : 24;
    const int nj = 32 - jstart;

    const __nv_bfloat16* kvsrc[4] = {
        Kh + (size_t)bh * Ll * 64, Kl + (size_t)bh * Ll * 64,
        Vh + (size_t)bh * Ll * 64, Vl + (size_t)bh * Ll * 64 };

    {
        const int kt = jstart * 64;
#pragma unroll
        for (int i = 0; i < 16; i++) {
            int idx = i * 128 + tid;
            int t = idx >> 9, r = (idx >> 3) & 63, cc = idx & 7;
            cpa16(sb + oKV + t * ATILE_B + (uint32_t)(r * QSTR + cc * 8) * 2,
                  kvsrc[t] + (size_t)(kt + r) * 64 + cc * 8);
        }
        asm volatile("cp.async.commit_group;");
    }

    asm volatile("cp.async.wait_group 1;");
    __syncthreads();

    uint32_t fqh[4][4], fql[4][4];
    {
        const uint32_t qaddr = sb + oQ +
            (uint32_t)((wid * 16 + (lane & 15)) * QSTR + (lane >> 4) * 8) * 2;
#pragma unroll
        for (int c = 0; c < 4; c++) {
            ldsm_x4(fqh[c], qaddr + c * 32);
            ldsm_x4(fql[c], qaddr + ATILE_B + c * 32);
        }
    }

    float m1 = -5e29f, m2 = -5e29f, l1 = 0.f, l2 = 0.f;
    float acc[8][4];
#pragma unroll
    for (int j = 0; j < 8; j++)
#pragma unroll
        for (int d = 0; d < 4; d++) acc[j][d] = 0.f;

    const int r1 = q0 + wid * 16 + (lane >> 2);

    const uint32_t kaddr0 = (uint32_t)((((lane >> 4) << 3) + (lane & 7)) * QSTR
                                        + ((lane >> 3) & 1) * 8) * 2;
    const uint32_t vaddr0 = (uint32_t)((lane & 15) * QSTR + (lane >> 4) * 8) * 2;

    for (int tix = 0; tix < nj; tix++) {
        const int kt = (jstart + tix) * 64;
        const int st = tix & 1;

        if (tix + 1 < nj) {
            const int ktn = kt + 64;
            const uint32_t soff = oKV + (st ^ 1) * AKV_B;
#pragma unroll
            for (int i = 0; i < 16; i++) {
                int idx = i * 128 + tid;
                int t = idx >> 9, r = (idx >> 3) & 63, cc = idx & 7;
                cpa16(sb + soff + t * ATILE_B + (uint32_t)(r * QSTR + cc * 8) * 2,
                      kvsrc[t] + (size_t)(ktn + r) * 64 + cc * 8);
            }
            asm volatile("cp.async.commit_group;");
            asm volatile("cp.async.wait_group 1;");
        } else {
            asm volatile("cp.async.wait_group 0;");
        }
        __syncthreads();

        const uint32_t sKh = sb + oKV + st * AKV_B;
        const uint32_t sKl = sKh + ATILE_B;
        const uint32_t sVh = sKh + 2 * ATILE_B;
        const uint32_t sVl = sKh + 3 * ATILE_B;

        float s[8][4];
#pragma unroll
        for (int jb = 0; jb < 8; jb++)
#pragma unroll
            for (int d = 0; d < 4; d++) s[jb][d] = 0.f;

        {
            uint32_t khf[2][4], klf[2][4];
            ldsm_x4(khf[0], sKh + kaddr0);
            ldsm_x4(klf[0], sKl + kaddr0);
#pragma unroll
            for (int ix = 0; ix < 16; ix++) {
                const int c  = ix >> 2;
                const int nt = ix & 3;
                const int cur = ix & 1;
                if (ix < 15) {
                    const int cn  = (ix + 1) >> 2;
                    const int ntn = (ix + 1) & 3;
                    const uint32_t noff = (uint32_t)(ntn * 16 * QSTR * 2) + cn * 32;
                    ldsm_x4(khf[cur ^ 1], sKh + kaddr0 + noff);
                    ldsm_x4(klf[cur ^ 1], sKl + kaddr0 + noff);
                }
                mma16816(s[nt * 2 + 0], fqh[c], &khf[cur][0]);
                mma16816(s[nt * 2 + 1], fqh[c], &khf[cur][2]);
                mma16816(s[nt * 2 + 0], fqh[c], &klf[cur][0]);
                mma16816(s[nt * 2 + 1], fqh[c], &klf[cur][2]);
                mma16816(s[nt * 2 + 0], fql[c], &khf[cur][0]);
                mma16816(s[nt * 2 + 1], fql[c], &khf[cur][2]);
            }
        }

        if (kt == q0 && kt < PAD) {
            const int cbase = kt + 2 * (lane & 3);
#pragma unroll
            for (int jb = 0; jb < 8; jb++) {
                const int c0 = cbase + jb * 8;
                s[jb][0] = (c0     > r1) ? s[jb][0] : -1e30f;
                s[jb][1] = (c0 + 1 > r1) ? s[jb][1] : -1e30f;
                s[jb][2] = (c0     > r1 + 8) ? s[jb][2] : -1e30f;
                s[jb][3] = (c0 + 1 > r1 + 8) ? s[jb][3] : -1e30f;
            }
        }

        float t1 = -1e30f, t2 = -1e30f;
#pragma unroll
        for (int jb = 0; jb < 8; jb++) {
            t1 = fmaxf(t1, fmaxf(s[jb][0], s[jb][1]));
            t2 = fmaxf(t2, fmaxf(s[jb][2], s[jb][3]));
        }
        t1 = fmaxf(t1, __shfl_xor_sync(0xffffffffu, t1, 1));
        t1 = fmaxf(t1, __shfl_xor_sync(0xffffffffu, t1, 2));
        t2 = fmaxf(t2, __shfl_xor_sync(0xffffffffu, t2, 1));
        t2 = fmaxf(t2, __shfl_xor_sync(0xffffffffu, t2, 2));

        const float mn1 = fmaxf(m1, t1);
        const float mn2 = fmaxf(m2, t2);
        const float a1 = __expf(m1 - mn1);
        const float a2 = __expf(m2 - mn2);
        m1 = mn1; m2 = mn2;

        float sum1 = 0.f, sum2 = 0.f;
#pragma unroll
        for (int jb = 0; jb < 8; jb++) {
            s[jb][0] = __expf(s[jb][0] - mn1);
            s[jb][1] = __expf(s[jb][1] - mn1);
            s[jb][2] = __expf(s[jb][2] - mn2);
            s[jb][3] = __expf(s[jb][3] - mn2);
            sum1 += s[jb][0] + s[jb][1];
            sum2 += s[jb][2] + s[jb][3];
        }
        sum1 += __shfl_xor_sync(0xffffffffu, sum1, 1);
        sum1 += __shfl_xor_sync(0xffffffffu, sum1, 2);
        sum2 += __shfl_xor_sync(0xffffffffu, sum2, 1);
        sum2 += __shfl_xor_sync(0xffffffffu, sum2, 2);
        l1 = l1 * a1 + sum1;
        l2 = l2 * a2 + sum2;

#pragma unroll
        for (int jb = 0; jb < 8; jb++) {
            acc[jb][0] *= a1; acc[jb][1] *= a1;
            acc[jb][2] *= a2; acc[jb][3] *= a2;
        }

        uint32_t fph[4][4], fpl[4][4];
#pragma unroll
        for (int c = 0; c < 4; c++) {
            const float* p0 = s[2 * c];
            const float* p1 = s[2 * c + 1];
            fph[c][0] = packbf(p0[0], p0[1]);
            fph[c][1] = packbf(p0[2], p0[3]);
            fph[c][2] = packbf(p1[0], p1[1]);
            fph[c][3] = packbf(p1[2], p1[3]);
#pragma unroll
            for (int r = 0; r < 4; r++) {
                __nv_bfloat162 hb = *(__nv_bfloat162*)&fph[c][r];
                const float* src = (r < 2) ? p0 : p1;
                const int o = (r & 1) * 2;
                fpl[c][r] = packbf(src[o] - __bfloat162float(hb.x),
                                   src[o + 1] - __bfloat162float(hb.y));
            }
        }

        {
            uint32_t vhf[2][4], vlf[2][4];
            ldsm_x4_t(vhf[0], sVh + vaddr0);
            ldsm_x4_t(vlf[0], sVl + vaddr0);
#pragma unroll
            for (int ix = 0; ix < 16; ix++) {
                const int c  = ix >> 2;
                const int ng = ix & 3;
                const int cur = ix & 1;
                if (ix < 15) {
                    const int cn  = (ix + 1) >> 2;
                    const int ngn = (ix + 1) & 3;
                    const uint32_t aoff = (uint32_t)(cn * 16 * QSTR * 2) + vaddr0
                                        + (uint32_t)(ngn * 16 * 2);
                    ldsm_x4_t(vhf[cur ^ 1], sVh + aoff);
                    ldsm_x4_t(vlf[cur ^ 1], sVl + aoff);
                }
                mma16816(acc[ng * 2 + 0], fph[c], &vhf[cur][0]);
                mma16816(acc[ng * 2 + 1], fph[c], &vhf[cur][2]);
                mma16816(acc[ng * 2 + 0], fph[c], &vlf[cur][0]);
                mma16816(acc[ng * 2 + 1], fph[c], &vlf[cur][2]);
                mma16816(acc[ng * 2 + 0], fpl[c], &vhf[cur][0]);
                mma16816(acc[ng * 2 + 1], fpl[c], &vhf[cur][2]);
            }
        }
        __syncthreads();
    }

    // ---- epilogue: split to fp16 hi/lo, write out-proj A buffers ----
    const int b = bh >> 4;
    const int hh = bh & 15;
    const float inv1 = 1.f / l1;
    const float inv2 = 1.f / l2;
    const size_t row1 = (size_t)(b * Ll) + r1;
    const int col0 = hh * 64 + 2 * (lane & 3);
    __half2* H1 = (__half2*)OAh + row1 * (Dm / 2) + (col0 >> 1);
    __half2* L1 = (__half2*)OAl + row1 * (Dm / 2) + (col0 >> 1);
    __half2* H2 = H1 + 8 * (Dm / 2);
    __half2* L2 = L1 + 8 * (Dm / 2);
#pragma unroll
    for (int jb = 0; jb < 8; jb++) {
        float2 w1, w2;
        w1.x = acc[jb][0] * inv1; w1.y = acc[jb][1] * inv1;
        w2.x = acc[jb][2] * inv2; w2.y = acc[jb][3] * inv2;
        __half2 hv, lv;
        split2h(w1, hv, lv); H1[jb * 4] = hv; L1[jb * 4] = lv;
        split2h(w2, hv, lv); H2[jb * 4] = hv; L2[jb * 4] = lv;
    }
}

// ---------------------------------------------------------------------------
// Launch
// Inputs (metadata order): x, pad_mask, Wqkv, bqkv, Wout, bout
// ---------------------------------------------------------------------------
extern "C" void kernel_launch(void* const* d_in, const int* in_sizes, int n_in,
                              void* d_out, int out_size)
{
    const float* x    = (const float*)d_in[0];
    const float* Wqkv = (const float*)d_in[2];
    const float* bqkv = (const float*)d_in[3];
    const float* Wout = (const float*)d_in[4];
    const float* bout = (const float*)d_in[5];
    float* out = (float*)d_out;

    __half *ah, *al, *bw;
    __nv_bfloat16 *qh, *ql, *kh, *kl, *vh, *vl;
    float2* rt;
    cudaGetSymbolAddress((void**)&ah, g_ah);
    cudaGetSymbolAddress((void**)&al, g_al);
    cudaGetSymbolAddress((void**)&bw, g_bw);
    cudaGetSymbolAddress((void**)&qh, g_qh);
    cudaGetSymbolAddress((void**)&ql, g_ql);
    cudaGetSymbolAddress((void**)&kh, g_kh);
    cudaGetSymbolAddress((void**)&kl, g_kl);
    cudaGetSymbolAddress((void**)&vh, g_vh);
    cudaGetSymbolAddress((void**)&vl, g_vl);
    cudaGetSymbolAddress((void**)&rt, g_rope);

    cudaFuncSetAttribute(gemm_mma_split<0>, cudaFuncAttributeMaxDynamicSharedMemorySize, GSMEM);
    cudaFuncSetAttribute(gemm_mma_split<1>, cudaFuncAttributeMaxDynamicSharedMemorySize, GSMEM);
    cudaFuncSetAttribute(attn_mma, cudaFuncAttributeMaxDynamicSharedMemorySize, ASMEM);

    // 1) rope table + split x (fp16 2-term) + convert Wqkv (fp16)
    {
        rope_table<<<(Ll * 32 + 255) / 256, 256>>>(rt);
        int n2 = (Mrows * Dm) / 2;
        split_fp16<<<(n2 + 255) / 256, 256>>>(x, ah, al, n2);
        n2 = (QKVN * Dm) / 2;
        cvt_fp16<<<(n2 + 255) / 256, 256>>>(Wqkv, bw, n2);
    }
    // 2) QKV projection + bias + RoPE + bf16-split scatter
    {
        dim3 grid(QKVN / 128, Mrows / 128);
        gemm_mma_split<1><<<grid, 256, GSMEM>>>(ah, al, bw, bqkv, nullptr,
                                                qh, ql, kh, kl, vh, vl, rt,
                                                Mrows, QKVN, Dm);
    }
    // 3) attention (writes fp16 hi/lo out-proj A directly)
    {
        dim3 grid(Ll / 64, Bb * Hh);
        attn_mma<<<grid, 128, ASMEM>>>(qh, ql, kh, kl, vh, vl, ah, al);
    }
    // 4) convert Wout (fp16)
    {
        int n2 = (Dm * Dm) / 2;
        cvt_fp16<<<(n2 + 255) / 256, 256>>>(Wout, bw, n2);
    }
    // 5) output projection + bias
    {
        dim3 grid(Dm / 128, Mrows / 128);
        gemm_mma_split<0><<<grid, 256, GSMEM>>>(ah, al, bw, bout, out,
                                                nullptr, nullptr, nullptr, nullptr,
                                                nullptr, nullptr, nullptr,
                                                Mrows, Dm, Dm);
    }
}

// round 14
// speedup vs baseline: 1.5132x; 1.2469x over previous
#include <cuda_runtime.h>
#include <cuda_bf16.h>
#include <cuda_fp16.h>
#include <cstdint>
#include <math.h>

// Problem constants (fixed by the dataset)
#define Bb   2
#define Ll   2048
#define Dm   1024
#define Hh   16
#define DhD  64
#define PAD  1536
#define Mrows (Bb * Ll)          // 4096
#define QKVN  (3 * Dm)           // 3072

// ---------------------------------------------------------------------------
// Scratch (device globals; no runtime allocation allowed)
// ---------------------------------------------------------------------------
// fp16 A operand (x, then attn-out) and fp16 B operand (weights)
__device__ __half g_ax[(size_t)Mrows * Dm];
__device__ __half g_bw[(size_t)QKVN * Dm];
// bf16 hi/lo q/k/v in [B*H][L][64] layout (q pre-scaled by 1/8) for attention
#define QKVSZ ((size_t)Bb * Hh * Ll * DhD)
__device__ __nv_bfloat16 g_qh[QKVSZ], g_ql[QKVSZ];
__device__ __nv_bfloat16 g_kh[QKVSZ], g_kl[QKVSZ];
__device__ __nv_bfloat16 g_vh[QKVSZ], g_vl[QKVSZ];
__device__ float2 g_rope[Ll * 32];

// ---------------------------------------------------------------------------
// mma.sync helpers
// ---------------------------------------------------------------------------
__device__ __forceinline__ uint32_t smem_u32(const void* p) {
    uint32_t a;
    asm("{ .reg .u64 t; cvta.to.shared.u64 t, %1; cvt.u32.u64 %0, t; }" : "=r"(a) : "l"(p));
    return a;
}
__device__ __forceinline__ void ldsm_x4(uint32_t r[4], uint32_t addr) {
    asm volatile("ldmatrix.sync.aligned.m8n8.x4.shared.b16 {%0,%1,%2,%3}, [%4];"
                 : "=r"(r[0]), "=r"(r[1]), "=r"(r[2]), "=r"(r[3]) : "r"(addr));
}
__device__ __forceinline__ void ldsm_x4_t(uint32_t r[4], uint32_t addr) {
    asm volatile("ldmatrix.sync.aligned.m8n8.x4.trans.shared.b16 {%0,%1,%2,%3}, [%4];"
                 : "=r"(r[0]), "=r"(r[1]), "=r"(r[2]), "=r"(r[3]) : "r"(addr));
}
// bf16 mma (attention)
__device__ __forceinline__ void mma16816(float c[4], const uint32_t a[4], const uint32_t b[2]) {
    asm("mma.sync.aligned.m16n8k16.row.col.f32.bf16.bf16.f32 "
        "{%0,%1,%2,%3}, {%4,%5,%6,%7}, {%8,%9}, {%0,%1,%2,%3};"
        : "+f"(c[0]), "+f"(c[1]), "+f"(c[2]), "+f"(c[3])
        : "r"(a[0]), "r"(a[1]), "r"(a[2]), "r"(a[3]), "r"(b[0]), "r"(b[1]));
}
// fp16 mma (projection GEMMs)
__device__ __forceinline__ void mma16816h(float c[4], const uint32_t a[4], const uint32_t b[2]) {
    asm("mma.sync.aligned.m16n8k16.row.col.f32.f16.f16.f32 "
        "{%0,%1,%2,%3}, {%4,%5,%6,%7}, {%8,%9}, {%0,%1,%2,%3};"
        : "+f"(c[0]), "+f"(c[1]), "+f"(c[2]), "+f"(c[3])
        : "r"(a[0]), "r"(a[1]), "r"(a[2]), "r"(a[3]), "r"(b[0]), "r"(b[1]));
}
__device__ __forceinline__ void cpa16(uint32_t dst, const void* src) {
    asm volatile("cp.async.cg.shared.global [%0], [%1], 16;" :: "r"(dst), "l"(src));
}
__device__ __forceinline__ uint32_t packbf(float lo, float hi) {
    uint32_t r;
    asm("cvt.rn.bf16x2.f32 %0, %1, %2;" : "=r"(r) : "f"(hi), "f"(lo));
    return r;
}
__device__ __forceinline__ void split2(float2 v, __nv_bfloat162& h, __nv_bfloat162& l) {
    h.x = __float2bfloat16(v.x); h.y = __float2bfloat16(v.y);
    l.x = __float2bfloat16(v.x - __bfloat162float(h.x));
    l.y = __float2bfloat16(v.y - __bfloat162float(h.y));
}

// ---------------------------------------------------------------------------
// Kernel: fp32 -> fp16 convert
// ---------------------------------------------------------------------------
__global__ __launch_bounds__(256)
void cvt_fp16(const float* __restrict__ X, __half* __restrict__ H, int n2)
{
    int i = blockIdx.x * blockDim.x + threadIdx.x;
    if (i >= n2) return;
    float2 x = ((const float2*)X)[i];
    ((__half2*)H)[i] = __floats2half2_rn(x.x, x.y);
}

// ---------------------------------------------------------------------------
// Kernel: RoPE cos/sin table
// ---------------------------------------------------------------------------
__global__ __launch_bounds__(256)
void rope_table(float2* __restrict__ T)
{
    int idx = blockIdx.x * blockDim.x + threadIdx.x;
    if (idx >= Ll * 32) return;
    const int l = idx >> 5, j = idx & 31;
    const float inv_freq = __expf(-(float)j * (9.210340371976184f / 32.0f));
    float s, c;
    sincosf((float)l * inv_freq, &s, &c);
    T[idx] = make_float2(c, s);
}

// ---------------------------------------------------------------------------
// fp16 GEMM: C[M,N] = A[M,K] * B[N,K]^T + bias (single fp16 operands,
// fp32 accumulate). 2 smem tiles/stage, double-buffered cp.async.
// EPI=0: fp32 C+bias. EPI=1: fused bias+RoPE+bf16-split scatter to q/k/v.
// ---------------------------------------------------------------------------
#define PADW 40
#define KC   32
#define TILE_BYTES (128 * PADW * 2)
#define STAGE_BYTES (2 * TILE_BYTES)
#define GSMEM (2 * STAGE_BYTES)

template<int EPI>
__global__ __launch_bounds__(256, 2)
void gemm_mma_fp16(const __half* __restrict__ A, const __half* __restrict__ Bw,
                   const float* __restrict__ bias, float* __restrict__ C,
                   __nv_bfloat16* __restrict__ Qh, __nv_bfloat16* __restrict__ Ql,
                   __nv_bfloat16* __restrict__ Kh, __nv_bfloat16* __restrict__ Kl,
                   __nv_bfloat16* __restrict__ Vh, __nv_bfloat16* __restrict__ Vl,
                   const float2* __restrict__ Rt,
                   int M, int N, int K)
{
    extern __shared__ char dsm[];
    const uint32_t sbase = smem_u32(dsm);

    const int tid  = threadIdx.x;
    const int lane = tid & 31;
    const int wid  = tid >> 5;
    const int wm   = wid & 3;
    const int wn   = wid >> 2;
    const int m0   = blockIdx.y * 128;
    const int n0   = blockIdx.x * 128;

    float c[2][8][4];
#pragma unroll
    for (int i = 0; i < 2; i++)
#pragma unroll
        for (int j = 0; j < 8; j++)
#pragma unroll
            for (int q = 0; q < 4; q++) c[i][j][q] = 0.f;

    const int lr  = tid >> 2;
    const int lcc = (tid & 3) * 8;
    const __half* srcA = A  + (size_t)(m0 + lr) * K + lcc;
    const __half* srcB = Bw + (size_t)(n0 + lr) * K + lcc;
    const size_t rowskip = (size_t)64 * K;
    const uint32_t dst0 = sbase + (uint32_t)(lr * PADW + lcc) * 2;
    const uint32_t dst1 = dst0 + (uint32_t)(64 * PADW) * 2;

    const int arow = wm * 32 + (lane & 15);
    const int acol = (lane >> 4) * 8;
    const int brow = wn * 64 + ((lane >> 4) << 3) + (lane & 7);
    const int bcol = ((lane >> 3) & 1) * 8;
    const uint32_t aA = sbase + 0 * TILE_BYTES + (uint32_t)(arow * PADW + acol) * 2;
    const uint32_t aB = sbase + 1 * TILE_BYTES + (uint32_t)(brow * PADW + bcol) * 2;

    const int nch = K / KC;

    cpa16(dst0, srcA);
    cpa16(dst1, srcA + rowskip);
    cpa16(dst0 + TILE_BYTES, srcB);
    cpa16(dst1 + TILE_BYTES, srcB + rowskip);
    asm volatile("cp.async.commit_group;");

    for (int s = 0; s < nch; s++) {
        if (s + 1 < nch) {
            const uint32_t stoff = ((s + 1) & 1) * (uint32_t)STAGE_BYTES;
            const int koff = (s + 1) * KC;
            cpa16(dst0 + stoff, srcA + koff);
            cpa16(dst1 + stoff, srcA + koff + rowskip);
            cpa16(dst0 + stoff + TILE_BYTES, srcB + koff);
            cpa16(dst1 + stoff + TILE_BYTES, srcB + koff + rowskip);
            asm volatile("cp.async.commit_group;");
            asm volatile("cp.async.wait_group 1;");
        } else {
            asm volatile("cp.async.wait_group 0;");
        }
        __syncthreads();

        const uint32_t stoff = (s & 1) * (uint32_t)STAGE_BYTES;
#pragma unroll
        for (int ks = 0; ks < 2; ks++) {
            const uint32_t kb = (uint32_t)(ks * 16 * 2);
            uint32_t ahf[2][4];
#pragma unroll
            for (int mt = 0; mt < 2; mt++)
                ldsm_x4(ahf[mt], aA + stoff + (uint32_t)(mt * 16 * PADW * 2) + kb);
            // pipelined B fragments
            uint32_t bwf[2][4];
            ldsm_x4(bwf[0], aB + stoff + kb);
#pragma unroll
            for (int nt = 0; nt < 4; nt++) {
                const int cur = nt & 1;
                if (nt < 3) {
                    const uint32_t noff = stoff + (uint32_t)((nt + 1) * 16 * PADW * 2) + kb;
                    ldsm_x4(bwf[cur ^ 1], aB + noff);
                }
                mma16816h(c[0][nt * 2 + 0], ahf[0], &bwf[cur][0]);
                mma16816h(c[0][nt * 2 + 1], ahf[0], &bwf[cur][2]);
                mma16816h(c[1][nt * 2 + 0], ahf[1], &bwf[cur][0]);
                mma16816h(c[1][nt * 2 + 1], ahf[1], &bwf[cur][2]);
            }
        }
        __syncthreads();
    }

#pragma unroll
    for (int mt = 0; mt < 2; mt++) {
        const int mrow = m0 + wm * 32 + mt * 16 + (lane >> 2);
#pragma unroll
        for (int n8 = 0; n8 < 8; n8++) {
            const int ncol = n0 + wn * 64 + n8 * 8 + 2 * (lane & 3);
            float2 bb = *(const float2*)(bias + ncol);
            if (EPI == 0) {
                float2 o0, o1;
                o0.x = c[mt][n8][0] + bb.x; o0.y = c[mt][n8][1] + bb.y;
                o1.x = c[mt][n8][2] + bb.x; o1.y = c[mt][n8][3] + bb.y;
                *(float2*)&C[(size_t)mrow * N + ncol]       = o0;
                *(float2*)&C[(size_t)(mrow + 8) * N + ncol] = o1;
            } else {
                const int sec  = ncol >> 10;        // 0=q, 1=k, 2=v
                const int hcol = ncol & 1023;
                const int hh   = hcol >> 6;
                const int j    = (hcol & 63) >> 1;
                __nv_bfloat16* Hd = (sec == 0) ? Qh : (sec == 1) ? Kh : Vh;
                __nv_bfloat16* Ld = (sec == 0) ? Ql : (sec == 1) ? Kl : Vl;
#pragma unroll
                for (int r = 0; r < 2; r++) {
                    const int mr = mrow + r * 8;
                    const int l  = mr & (Ll - 1);
                    const int b  = mr >> 11;
                    float2 v;
                    v.x = c[mt][n8][2 * r]     + bb.x;
                    v.y = c[mt][n8][2 * r + 1] + bb.y;
                    if (sec < 2) {
                        const float2 cs = Rt[l * 32 + j];
                        float nx = v.x * cs.x - v.y * cs.y;
                        float ny = v.x * cs.y + v.y * cs.x;
                        if (sec == 0) { nx *= 0.125f; ny *= 0.125f; }
                        v.x = nx; v.y = ny;
                    }
                    __nv_bfloat162 hv, lv;
                    split2(v, hv, lv);
                    const size_t base = ((size_t)(b * Hh + hh) * Ll + l) * 32 + j;
                    ((__nv_bfloat162*)Hd)[base] = hv;
                    ((__nv_bfloat162*)Ld)[base] = lv;
                }
            }
        }
    }
}

// ---------------------------------------------------------------------------
// Flash attention with mma.sync bf16-split (inverted mask).
// Epilogue writes single fp16 into the out-proj A buffer.
// ---------------------------------------------------------------------------
#define QSTR 72
#define ATILE_B (64 * QSTR * 2)
#define AKV_B   (4 * ATILE_B)
#define ASMEM (2 * ATILE_B + 2 * AKV_B)

__global__ __launch_bounds__(128, 2)
void attn_mma(const __nv_bfloat16* __restrict__ Qh, const __nv_bfloat16* __restrict__ Ql,
              const __nv_bfloat16* __restrict__ Kh, const __nv_bfloat16* __restrict__ Kl,
              const __nv_bfloat16* __restrict__ Vh, const __nv_bfloat16* __restrict__ Vl,
              __half* __restrict__ OA)
{
    extern __shared__ char sm[];
    const uint32_t sb = smem_u32(sm);
    const int bh  = blockIdx.y;
    const int qt  = blockIdx.x;
    const int q0  = qt * 64;
    const int tid = threadIdx.x;
    const int lane = tid & 31;
    const int wid  = tid >> 5;

    const uint32_t oQ  = 0;
    const uint32_t oKV = 2 * ATILE_B;

    {
        const __nv_bfloat16* qsrc[2] = { Qh + ((size_t)bh * Ll + q0) * 64,
                                         Ql + ((size_t)bh * Ll + q0) * 64 };
#pragma unroll
        for (int i = 0; i < 8; i++) {
            int idx = i * 128 + tid;
            int t = idx >> 9, r = (idx >> 3) & 63, cc = idx & 7;
            cpa16(sb + oQ + t * ATILE_B + (uint32_t)(r * QSTR + cc * 8) * 2,
                  qsrc[t] + (size_t)r * 64 + cc * 8);
        }
        asm volatile("cp.async.commit_group;");
    }

    const int jstart = (qt < 24) ? qt : 24;
    const int nj = 32 - jstart;

    const __nv_bfloat16* kvsrc[4] = {
        Kh + (size_t)bh * Ll * 64, Kl + (size_t)bh * Ll * 64,
        Vh + (size_t)bh * Ll * 64, Vl + (size_t)bh * Ll * 64 };

    {
        const int kt = jstart * 64;
#pragma unroll
        for (int i = 0; i < 16; i++) {
            int idx = i * 128 + tid;
            int t = idx >> 9, r = (idx >> 3) & 63, cc = idx & 7;
            cpa16(sb + oKV + t * ATILE_B + (uint32_t)(r * QSTR + cc * 8) * 2,
                  kvsrc[t] + (size_t)(kt + r) * 64 + cc * 8);
        }
        asm volatile("cp.async.commit_group;");
    }

    asm volatile("cp.async.wait_group 1;");
    __syncthreads();

    uint32_t fqh[4][4], fql[4][4];
    {
        const uint32_t qaddr = sb + oQ +
            (uint32_t)((wid * 16 + (lane & 15)) * QSTR + (lane >> 4) * 8) * 2;
#pragma unroll
        for (int c = 0; c < 4; c++) {
            ldsm_x4(fqh[c], qaddr + c * 32);
            ldsm_x4(fql[c], qaddr + ATILE_B + c * 32);
        }
    }

    float m1 = -5e29f, m2 = -5e29f, l1 = 0.f, l2 = 0.f;
    float acc[8][4];
#pragma unroll
    for (int j = 0; j < 8; j++)
#pragma unroll
        for (int d = 0; d < 4; d++) acc[j][d] = 0.f;

    const int r1 = q0 + wid * 16 + (lane >> 2);

    const uint32_t kaddr0 = (uint32_t)((((lane >> 4) << 3) + (lane & 7)) * QSTR
                                        + ((lane >> 3) & 1) * 8) * 2;
    const uint32_t vaddr0 = (uint32_t)((lane & 15) * QSTR + (lane >> 4) * 8) * 2;

    for (int tix = 0; tix < nj; tix++) {
        const int kt = (jstart + tix) * 64;
        const int st = tix & 1;

        if (tix + 1 < nj) {
            const int ktn = kt + 64;
            const uint32_t soff = oKV + (st ^ 1) * AKV_B;
#pragma unroll
            for (int i = 0; i < 16; i++) {
                int idx = i * 128 + tid;
                int t = idx >> 9, r = (idx >> 3) & 63, cc = idx & 7;
                cpa16(sb + soff + t * ATILE_B + (uint32_t)(r * QSTR + cc * 8) * 2,
                      kvsrc[t] + (size_t)(ktn + r) * 64 + cc * 8);
            }
            asm volatile("cp.async.commit_group;");
            asm volatile("cp.async.wait_group 1;");
        } else {
            asm volatile("cp.async.wait_group 0;");
        }
        __syncthreads();

        const uint32_t sKh = sb + oKV + st * AKV_B;
        const uint32_t sKl = sKh + ATILE_B;
        const uint32_t sVh = sKh + 2 * ATILE_B;
        const uint32_t sVl = sKh + 3 * ATILE_B;

        float s[8][4];
#pragma unroll
        for (int jb = 0; jb < 8; jb++)
#pragma unroll
            for (int d = 0; d < 4; d++) s[jb][d] = 0.f;

        {
            uint32_t khf[2][4], klf[2][4];
            ldsm_x4(khf[0], sKh + kaddr0);
            ldsm_x4(klf[0], sKl + kaddr0);
#pragma unroll
            for (int ix = 0; ix < 16; ix++) {
                const int c  = ix >> 2;
                const int nt = ix & 3;
                const int cur = ix & 1;
                if (ix < 15) {
                    const int cn  = (ix + 1) >> 2;
                    const int ntn = (ix + 1) & 3;
                    const uint32_t noff = (uint32_t)(ntn * 16 * QSTR * 2) + cn * 32;
                    ldsm_x4(khf[cur ^ 1], sKh + kaddr0 + noff);
                    ldsm_x4(klf[cur ^ 1], sKl + kaddr0 + noff);
                }
                mma16816(s[nt * 2 + 0], fqh[c], &khf[cur][0]);
                mma16816(s[nt * 2 + 1], fqh[c], &khf[cur][2]);
                mma16816(s[nt * 2 + 0], fqh[c], &klf[cur][0]);
                mma16816(s[nt * 2 + 1], fqh[c], &klf[cur][2]);
                mma16816(s[nt * 2 + 0], fql[c], &khf[cur][0]);
                mma16816(s[nt * 2 + 1], fql[c], &khf[cur][2]);
            }
        }

        if (kt == q0 && kt < PAD) {
            const int cbase = kt + 2 * (lane & 3);
#pragma unroll
            for (int jb = 0; jb < 8; jb++) {
                const int c0 = cbase + jb * 8;
                s[jb][0] = (c0     > r1) ? s[jb][0] : -1e30f;
                s[jb][1] = (c0 + 1 > r1) ? s[jb][1] : -1e30f;
                s[jb][2] = (c0     > r1 + 8) ? s[jb][2] : -1e30f;
                s[jb][3] = (c0 + 1 > r1 + 8) ? s[jb][3] : -1e30f;
            }
        }

        float t1 = -1e30f, t2 = -1e30f;
#pragma unroll
        for (int jb = 0; jb < 8; jb++) {
            t1 = fmaxf(t1, fmaxf(s[jb][0], s[jb][1]));
            t2 = fmaxf(t2, fmaxf(s[jb][2], s[jb][3]));
        }
        t1 = fmaxf(t1, __shfl_xor_sync(0xffffffffu, t1, 1));
        t1 = fmaxf(t1, __shfl_xor_sync(0xffffffffu, t1, 2));
        t2 = fmaxf(t2, __shfl_xor_sync(0xffffffffu, t2, 1));
        t2 = fmaxf(t2, __shfl_xor_sync(0xffffffffu, t2, 2));

        const float mn1 = fmaxf(m1, t1);
        const float mn2 = fmaxf(m2, t2);
        const float a1 = __expf(m1 - mn1);
        const float a2 = __expf(m2 - mn2);
        m1 = mn1; m2 = mn2;

        float sum1 = 0.f, sum2 = 0.f;
#pragma unroll
        for (int jb = 0; jb < 8; jb++) {
            s[jb][0] = __expf(s[jb][0] - mn1);
            s[jb][1] = __expf(s[jb][1] - mn1);
            s[jb][2] = __expf(s[jb][2] - mn2);
            s[jb][3] = __expf(s[jb][3] - mn2);
            sum1 += s[jb][0] + s[jb][1];
            sum2 += s[jb][2] + s[jb][3];
        }
        sum1 += __shfl_xor_sync(0xffffffffu, sum1, 1);
        sum1 += __shfl_xor_sync(0xffffffffu, sum1, 2);
        sum2 += __shfl_xor_sync(0xffffffffu, sum2, 1);
        sum2 += __shfl_xor_sync(0xffffffffu, sum2, 2);
        l1 = l1 * a1 + sum1;
        l2 = l2 * a2 + sum2;

#pragma unroll
        for (int jb = 0; jb < 8; jb++) {
            acc[jb][0] *= a1; acc[jb][1] *= a1;
            acc[jb][2] *= a2; acc[jb][3] *= a2;
        }

        uint32_t fph[4][4], fpl[4][4];
#pragma unroll
        for (int c = 0; c < 4; c++) {
            const float* p0 = s[2 * c];
            const float* p1 = s[2 * c + 1];
            fph[c][0] = packbf(p0[0], p0[1]);
            fph[c][1] = packbf(p0[2], p0[3]);
            fph[c][2] = packbf(p1[0], p1[1]);
            fph[c][3] = packbf(p1[2], p1[3]);
#pragma unroll
            for (int r = 0; r < 4; r++) {
                __nv_bfloat162 hb = *(__nv_bfloat162*)&fph[c][r];
                const float* src = (r < 2) ? p0 : p1;
                const int o = (r & 1) * 2;
                fpl[c][r] = packbf(src[o] - __bfloat162float(hb.x),
                                   src[o + 1] - __bfloat162float(hb.y));
            }
        }

        {
            uint32_t vhf[2][4], vlf[2][4];
            ldsm_x4_t(vhf[0], sVh + vaddr0);
            ldsm_x4_t(vlf[0], sVl + vaddr0);
#pragma unroll
            for (int ix = 0; ix < 16; ix++) {
                const int c  = ix >> 2;
                const int ng = ix & 3;
                const int cur = ix & 1;
                if (ix < 15) {
                    const int cn  = (ix + 1) >> 2;
                    const int ngn = (ix + 1) & 3;
                    const uint32_t aoff = (uint32_t)(cn * 16 * QSTR * 2) + vaddr0
                                        + (uint32_t)(ngn * 16 * 2);
                    ldsm_x4_t(vhf[cur ^ 1], sVh + aoff);
                    ldsm_x4_t(vlf[cur ^ 1], sVl + aoff);
                }
                mma16816(acc[ng * 2 + 0], fph[c], &vhf[cur][0]);
                mma16816(acc[ng * 2 + 1], fph[c], &vhf[cur][2]);
                mma16816(acc[ng * 2 + 0], fph[c], &vlf[cur][0]);
                mma16816(acc[ng * 2 + 1], fph[c], &vlf[cur][2]);
                mma16816(acc[ng * 2 + 0], fpl[c], &vhf[cur][0]);
                mma16816(acc[ng * 2 + 1], fpl[c], &vhf[cur][2]);
            }
        }
        __syncthreads();
    }

    // ---- epilogue: write single fp16 into out-proj A buffer ----
    const int b = bh >> 4;
    const int hh = bh & 15;
    const float inv1 = 1.f / l1;
    const float inv2 = 1.f / l2;
    const size_t row1 = (size_t)(b * Ll) + r1;
    const int col0 = hh * 64 + 2 * (lane & 3);
    __half2* H1 = (__half2*)OA + row1 * (Dm / 2) + (col0 >> 1);
    __half2* H2 = H1 + 8 * (Dm / 2);
#pragma unroll
    for (int jb = 0; jb < 8; jb++) {
        H1[jb * 4] = __floats2half2_rn(acc[jb][0] * inv1, acc[jb][1] * inv1);
        H2[jb * 4] = __floats2half2_rn(acc[jb][2] * inv2, acc[jb][3] * inv2);
    }
}

// ---------------------------------------------------------------------------
// Launch
// Inputs (metadata order): x, pad_mask, Wqkv, bqkv, Wout, bout
// ---------------------------------------------------------------------------
extern "C" void kernel_launch(void* const* d_in, const int* in_sizes, int n_in,
                              void* d_out, int out_size)
{
    const float* x    = (const float*)d_in[0];
    const float* Wqkv = (const float*)d_in[2];
    const float* bqkv = (const float*)d_in[3];
    const float* Wout = (const float*)d_in[4];
    const float* bout = (const float*)d_in[5];
    float* out = (float*)d_out;

    __half *ax, *bw;
    __nv_bfloat16 *qh, *ql, *kh, *kl, *vh, *vl;
    float2* rt;
    cudaGetSymbolAddress((void**)&ax, g_ax);
    cudaGetSymbolAddress((void**)&bw, g_bw);
    cudaGetSymbolAddress((void**)&qh, g_qh);
    cudaGetSymbolAddress((void**)&ql, g_ql);
    cudaGetSymbolAddress((void**)&kh, g_kh);
    cudaGetSymbolAddress((void**)&kl, g_kl);
    cudaGetSymbolAddress((void**)&vh, g_vh);
    cudaGetSymbolAddress((void**)&vl, g_vl);
    cudaGetSymbolAddress((void**)&rt, g_rope);

    cudaFuncSetAttribute(gemm_mma_fp16<0>, cudaFuncAttributeMaxDynamicSharedMemorySize, GSMEM);
    cudaFuncSetAttribute(gemm_mma_fp16<1>, cudaFuncAttributeMaxDynamicSharedMemorySize, GSMEM);
    cudaFuncSetAttribute(attn_mma, cudaFuncAttributeMaxDynamicSharedMemorySize, ASMEM);

    // 1) rope table + convert x and Wqkv to fp16
    {
        rope_table<<<(Ll * 32 + 255) / 256, 256>>>(rt);
        int n2 = (Mrows * Dm) / 2;
        cvt_fp16<<<(n2 + 255) / 256, 256>>>(x, ax, n2);
        n2 = (QKVN * Dm) / 2;
        cvt_fp16<<<(n2 + 255) / 256, 256>>>(Wqkv, bw, n2);
    }
    // 2) QKV projection + bias + RoPE + bf16-split scatter
    {
        dim3 grid(QKVN / 128, Mrows / 128);
        gemm_mma_fp16<1><<<grid, 256, GSMEM>>>(ax, bw, bqkv, nullptr,
                                               qh, ql, kh, kl, vh, vl, rt,
                                               Mrows, QKVN, Dm);
    }
    // 3) attention (writes fp16 out-proj A directly)
    {
        dim3 grid(Ll / 64, Bb * Hh);
        attn_mma<<<grid, 128, ASMEM>>>(qh, ql, kh, kl, vh, vl, ax);
    }
    // 4) convert Wout (fp16)
    {
        int n2 = (Dm * Dm) / 2;
        cvt_fp16<<<(n2 + 255) / 256, 256>>>(Wout, bw, n2);
    }
    // 5) output projection + bias
    {
        dim3 grid(Dm / 128, Mrows / 128);
        gemm_mma_fp16<0><<<grid, 256, GSMEM>>>(ax, bw, bout, out,
                                               nullptr, nullptr, nullptr, nullptr,
                                               nullptr, nullptr, nullptr,
                                               Mrows, Dm, Dm);
    }
}

// round 15
// speedup vs baseline: 1.5903x; 1.0509x over previous
#include <cuda_runtime.h>
#include <cuda_bf16.h>
#include <cuda_fp16.h>
#include <cstdint>
#include <math.h>

// Problem constants (fixed by the dataset)
#define Bb   2
#define Ll   2048
#define Dm   1024
#define Hh   16
#define DhD  64
#define PAD  1536
#define Mrows (Bb * Ll)          // 4096
#define QKVN  (3 * Dm)           // 3072

// ---------------------------------------------------------------------------
// Scratch (device globals; no runtime allocation allowed)
// ---------------------------------------------------------------------------
__device__ __half g_ax[(size_t)Mrows * Dm];
__device__ __half g_bw[(size_t)QKVN * Dm];
#define QKVSZ ((size_t)Bb * Hh * Ll * DhD)
__device__ __nv_bfloat16 g_qh[QKVSZ], g_ql[QKVSZ];
__device__ __nv_bfloat16 g_kh[QKVSZ], g_kl[QKVSZ];
__device__ __nv_bfloat16 g_vh[QKVSZ], g_vl[QKVSZ];
__device__ float2 g_rope[Ll * 32];

// ---------------------------------------------------------------------------
// mma.sync helpers
// ---------------------------------------------------------------------------
__device__ __forceinline__ uint32_t smem_u32(const void* p) {
    uint32_t a;
    asm("{ .reg .u64 t; cvta.to.shared.u64 t, %1; cvt.u32.u64 %0, t; }" : "=r"(a) : "l"(p));
    return a;
}
__device__ __forceinline__ void ldsm_x4(uint32_t r[4], uint32_t addr) {
    asm volatile("ldmatrix.sync.aligned.m8n8.x4.shared.b16 {%0,%1,%2,%3}, [%4];"
                 : "=r"(r[0]), "=r"(r[1]), "=r"(r[2]), "=r"(r[3]) : "r"(addr));
}
__device__ __forceinline__ void ldsm_x4_t(uint32_t r[4], uint32_t addr) {
    asm volatile("ldmatrix.sync.aligned.m8n8.x4.trans.shared.b16 {%0,%1,%2,%3}, [%4];"
                 : "=r"(r[0]), "=r"(r[1]), "=r"(r[2]), "=r"(r[3]) : "r"(addr));
}
// bf16 mma (attention)
__device__ __forceinline__ void mma16816(float c[4], const uint32_t a[4], const uint32_t b[2]) {
    asm("mma.sync.aligned.m16n8k16.row.col.f32.bf16.bf16.f32 "
        "{%0,%1,%2,%3}, {%4,%5,%6,%7}, {%8,%9}, {%0,%1,%2,%3};"
        : "+f"(c[0]), "+f"(c[1]), "+f"(c[2]), "+f"(c[3])
        : "r"(a[0]), "r"(a[1]), "r"(a[2]), "r"(a[3]), "r"(b[0]), "r"(b[1]));
}
// fp16 mma (projection GEMMs)
__device__ __forceinline__ void mma16816h(float c[4], const uint32_t a[4], const uint32_t b[2]) {
    asm("mma.sync.aligned.m16n8k16.row.col.f32.f16.f16.f32 "
        "{%0,%1,%2,%3}, {%4,%5,%6,%7}, {%8,%9}, {%0,%1,%2,%3};"
        : "+f"(c[0]), "+f"(c[1]), "+f"(c[2]), "+f"(c[3])
        : "r"(a[0]), "r"(a[1]), "r"(a[2]), "r"(a[3]), "r"(b[0]), "r"(b[1]));
}
__device__ __forceinline__ void cpa16(uint32_t dst, const void* src) {
    asm volatile("cp.async.cg.shared.global [%0], [%1], 16;" :: "r"(dst), "l"(src));
}
__device__ __forceinline__ uint32_t packbf(float lo, float hi) {
    uint32_t r;
    asm("cvt.rn.bf16x2.f32 %0, %1, %2;" : "=r"(r) : "f"(hi), "f"(lo));
    return r;
}
__device__ __forceinline__ void split2(float2 v, __nv_bfloat162& h, __nv_bfloat162& l) {
    h.x = __float2bfloat16(v.x); h.y = __float2bfloat16(v.y);
    l.x = __float2bfloat16(v.x - __bfloat162float(h.x));
    l.y = __float2bfloat16(v.y - __bfloat162float(h.y));
}

// ---------------------------------------------------------------------------
// Kernel: fp32 -> fp16 convert
// ---------------------------------------------------------------------------
__global__ __launch_bounds__(256)
void cvt_fp16(const float* __restrict__ X, __half* __restrict__ H, int n2)
{
    int i = blockIdx.x * blockDim.x + threadIdx.x;
    if (i >= n2) return;
    float2 x = ((const float2*)X)[i];
    ((__half2*)H)[i] = __floats2half2_rn(x.x, x.y);
}

// ---------------------------------------------------------------------------
// Kernel: RoPE cos/sin table
// ---------------------------------------------------------------------------
__global__ __launch_bounds__(256)
void rope_table(float2* __restrict__ T)
{
    int idx = blockIdx.x * blockDim.x + threadIdx.x;
    if (idx >= Ll * 32) return;
    const int l = idx >> 5, j = idx & 31;
    const float inv_freq = __expf(-(float)j * (9.210340371976184f / 32.0f));
    float s, c;
    sincosf((float)l * inv_freq, &s, &c);
    T[idx] = make_float2(c, s);
}

// ---------------------------------------------------------------------------
// fp16 GEMM: C[M,N] = A[M,K] * B[N,K]^T + bias, KC=64 (halved barrier count),
// 2 smem tiles/stage (A,B), double-buffered cp.async, 2 CTAs/SM.
// EPI=0: fp32 C+bias. EPI=1: fused bias+RoPE+bf16-split scatter to q/k/v.
// ---------------------------------------------------------------------------
#define PADW 72                      // 64 halfs + 8 pad -> 144B row stride
#define KC   64
#define TILE_BYTES (128 * PADW * 2)  // 18432
#define STAGE_BYTES (2 * TILE_BYTES) // 36864
#define GSMEM (2 * STAGE_BYTES)      // 73728

template<int EPI>
__global__ __launch_bounds__(256, 2)
void gemm_mma_fp16(const __half* __restrict__ A, const __half* __restrict__ Bw,
                   const float* __restrict__ bias, float* __restrict__ C,
                   __nv_bfloat16* __restrict__ Qh, __nv_bfloat16* __restrict__ Ql,
                   __nv_bfloat16* __restrict__ Kh, __nv_bfloat16* __restrict__ Kl,
                   __nv_bfloat16* __restrict__ Vh, __nv_bfloat16* __restrict__ Vl,
                   const float2* __restrict__ Rt,
                   int M, int N, int K)
{
    extern __shared__ char dsm[];
    const uint32_t sbase = smem_u32(dsm);

    const int tid  = threadIdx.x;
    const int lane = tid & 31;
    const int wid  = tid >> 5;
    const int wm   = wid & 3;
    const int wn   = wid >> 2;
    const int m0   = blockIdx.y * 128;
    const int n0   = blockIdx.x * 128;

    float c[2][8][4];
#pragma unroll
    for (int i = 0; i < 2; i++)
#pragma unroll
        for (int j = 0; j < 8; j++)
#pragma unroll
            for (int q = 0; q < 4; q++) c[i][j][q] = 0.f;

    // loader: tile = 128 rows x 64 halfs = 1024 x 16B chunks; 4 per thread
    // chunk idx = i*256 + tid, i in 0..3 -> row = i*32 + (tid>>3), col = tid&7
    const int r0  = tid >> 3;           // 0..31
    const int cc8 = (tid & 7) * 8;      // half offset within row
    const __half* srcA = A  + (size_t)(m0 + r0) * K + cc8;
    const __half* srcB = Bw + (size_t)(n0 + r0) * K + cc8;
    const uint32_t dstA = sbase + (uint32_t)(r0 * PADW + cc8) * 2;
    const uint32_t dstB = dstA + (uint32_t)TILE_BYTES;
    const size_t rstep = (size_t)32 * K;              // +32 rows
    const uint32_t dstep = (uint32_t)(32 * PADW * 2);

    const int arow = wm * 32 + (lane & 15);
    const int acol = (lane >> 4) * 8;
    const int brow = wn * 64 + ((lane >> 4) << 3) + (lane & 7);
    const int bcol = ((lane >> 3) & 1) * 8;
    const uint32_t aA = sbase + 0 * TILE_BYTES + (uint32_t)(arow * PADW + acol) * 2;
    const uint32_t aB = sbase + 1 * TILE_BYTES + (uint32_t)(brow * PADW + bcol) * 2;

    const int nch = K / KC;   // 16

#pragma unroll
    for (int i = 0; i < 4; i++) {
        cpa16(dstA + i * dstep, srcA + (size_t)i * rstep);
        cpa16(dstB + i * dstep, srcB + (size_t)i * rstep);
    }
    asm volatile("cp.async.commit_group;");

    for (int s = 0; s < nch; s++) {
        if (s + 1 < nch) {
            const uint32_t stoff = ((s + 1) & 1) * (uint32_t)STAGE_BYTES;
            const int koff = (s + 1) * KC;
#pragma unroll
            for (int i = 0; i < 4; i++) {
                cpa16(dstA + stoff + i * dstep, srcA + koff + (size_t)i * rstep);
                cpa16(dstB + stoff + i * dstep, srcB + koff + (size_t)i * rstep);
            }
            asm volatile("cp.async.commit_group;");
            asm volatile("cp.async.wait_group 1;");
        } else {
            asm volatile("cp.async.wait_group 0;");
        }
        __syncthreads();

        const uint32_t stoff = (s & 1) * (uint32_t)STAGE_BYTES;
#pragma unroll
        for (int ks = 0; ks < 4; ks++) {
            const uint32_t kb = (uint32_t)(ks * 16 * 2);
            uint32_t ahf[2][4];
#pragma unroll
            for (int mt = 0; mt < 2; mt++)
                ldsm_x4(ahf[mt], aA + stoff + (uint32_t)(mt * 16 * PADW * 2) + kb);
            uint32_t bwf[2][4];
            ldsm_x4(bwf[0], aB + stoff + kb);
#pragma unroll
            for (int nt = 0; nt < 4; nt++) {
                const int cur = nt & 1;
                if (nt < 3) {
                    const uint32_t noff = stoff + (uint32_t)((nt + 1) * 16 * PADW * 2) + kb;
                    ldsm_x4(bwf[cur ^ 1], aB + noff);
                }
                mma16816h(c[0][nt * 2 + 0], ahf[0], &bwf[cur][0]);
                mma16816h(c[0][nt * 2 + 1], ahf[0], &bwf[cur][2]);
                mma16816h(c[1][nt * 2 + 0], ahf[1], &bwf[cur][0]);
                mma16816h(c[1][nt * 2 + 1], ahf[1], &bwf[cur][2]);
            }
        }
        __syncthreads();
    }

#pragma unroll
    for (int mt = 0; mt < 2; mt++) {
        const int mrow = m0 + wm * 32 + mt * 16 + (lane >> 2);
#pragma unroll
        for (int n8 = 0; n8 < 8; n8++) {
            const int ncol = n0 + wn * 64 + n8 * 8 + 2 * (lane & 3);
            float2 bb = *(const float2*)(bias + ncol);
            if (EPI == 0) {
                float2 o0, o1;
                o0.x = c[mt][n8][0] + bb.x; o0.y = c[mt][n8][1] + bb.y;
                o1.x = c[mt][n8][2] + bb.x; o1.y = c[mt][n8][3] + bb.y;
                *(float2*)&C[(size_t)mrow * N + ncol]       = o0;
                *(float2*)&C[(size_t)(mrow + 8) * N + ncol] = o1;
            } else {
                const int sec  = ncol >> 10;        // 0=q, 1=k, 2=v
                const int hcol = ncol & 1023;
                const int hh   = hcol >> 6;
                const int j    = (hcol & 63) >> 1;
                __nv_bfloat16* Hd = (sec == 0) ? Qh : (sec == 1) ? Kh : Vh;
                __nv_bfloat16* Ld = (sec == 0) ? Ql : (sec == 1) ? Kl : Vl;
#pragma unroll
                for (int r = 0; r < 2; r++) {
                    const int mr = mrow + r * 8;
                    const int l  = mr & (Ll - 1);
                    const int b  = mr >> 11;
                    float2 v;
                    v.x = c[mt][n8][2 * r]     + bb.x;
                    v.y = c[mt][n8][2 * r + 1] + bb.y;
                    if (sec < 2) {
                        const float2 cs = Rt[l * 32 + j];
                        float nx = v.x * cs.x - v.y * cs.y;
                        float ny = v.x * cs.y + v.y * cs.x;
                        if (sec == 0) { nx *= 0.125f; ny *= 0.125f; }
                        v.x = nx; v.y = ny;
                    }
                    __nv_bfloat162 hv, lv;
                    split2(v, hv, lv);
                    const size_t base = ((size_t)(b * Hh + hh) * Ll + l) * 32 + j;
                    ((__nv_bfloat162*)Hd)[base] = hv;
                    ((__nv_bfloat162*)Ld)[base] = lv;
                }
            }
        }
    }
}

// ---------------------------------------------------------------------------
// Flash attention with mma.sync bf16-split (inverted mask).
// Epilogue writes single fp16 into the out-proj A buffer.
// ---------------------------------------------------------------------------
#define QSTR 72
#define ATILE_B (64 * QSTR * 2)
#define AKV_B   (4 * ATILE_B)
#define ASMEM (2 * ATILE_B + 2 * AKV_B)

__global__ __launch_bounds__(128, 2)
void attn_mma(const __nv_bfloat16* __restrict__ Qh, const __nv_bfloat16* __restrict__ Ql,
              const __nv_bfloat16* __restrict__ Kh, const __nv_bfloat16* __restrict__ Kl,
              const __nv_bfloat16* __restrict__ Vh, const __nv_bfloat16* __restrict__ Vl,
              __half* __restrict__ OA)
{
    extern __shared__ char sm[];
    const uint32_t sb = smem_u32(sm);
    const int bh  = blockIdx.y;
    const int qt  = blockIdx.x;
    const int q0  = qt * 64;
    const int tid = threadIdx.x;
    const int lane = tid & 31;
    const int wid  = tid >> 5;

    const uint32_t oQ  = 0;
    const uint32_t oKV = 2 * ATILE_B;

    {
        const __nv_bfloat16* qsrc[2] = { Qh + ((size_t)bh * Ll + q0) * 64,
                                         Ql + ((size_t)bh * Ll + q0) * 64 };
#pragma unroll
        for (int i = 0; i < 8; i++) {
            int idx = i * 128 + tid;
            int t = idx >> 9, r = (idx >> 3) & 63, cc = idx & 7;
            cpa16(sb + oQ + t * ATILE_B + (uint32_t)(r * QSTR + cc * 8) * 2,
                  qsrc[t] + (size_t)r * 64 + cc * 8);
        }
        asm volatile("cp.async.commit_group;");
    }

    const int jstart = (qt < 24) ? qt : 24;
    const int nj = 32 - jstart;

    const __nv_bfloat16* kvsrc[4] = {
        Kh + (size_t)bh * Ll * 64, Kl + (size_t)bh * Ll * 64,
        Vh + (size_t)bh * Ll * 64, Vl + (size_t)bh * Ll * 64 };

    {
        const int kt = jstart * 64;
#pragma unroll
        for (int i = 0; i < 16; i++) {
            int idx = i * 128 + tid;
            int t = idx >> 9, r = (idx >> 3) & 63, cc = idx & 7;
            cpa16(sb + oKV + t * ATILE_B + (uint32_t)(r * QSTR + cc * 8) * 2,
                  kvsrc[t] + (size_t)(kt + r) * 64 + cc * 8);
        }
        asm volatile("cp.async.commit_group;");
    }

    asm volatile("cp.async.wait_group 1;");
    __syncthreads();

    uint32_t fqh[4][4], fql[4][4];
    {
        const uint32_t qaddr = sb + oQ +
            (uint32_t)((wid * 16 + (lane & 15)) * QSTR + (lane >> 4) * 8) * 2;
#pragma unroll
        for (int c = 0; c < 4; c++) {
            ldsm_x4(fqh[c], qaddr + c * 32);
            ldsm_x4(fql[c], qaddr + ATILE_B + c * 32);
        }
    }

    float m1 = -5e29f, m2 = -5e29f, l1 = 0.f, l2 = 0.f;
    float acc[8][4];
#pragma unroll
    for (int j = 0; j < 8; j++)
#pragma unroll
        for (int d = 0; d < 4; d++) acc[j][d] = 0.f;

    const int r1 = q0 + wid * 16 + (lane >> 2);

    const uint32_t kaddr0 = (uint32_t)((((lane >> 4) << 3) + (lane & 7)) * QSTR
                                        + ((lane >> 3) & 1) * 8) * 2;
    const uint32_t vaddr0 = (uint32_t)((lane & 15) * QSTR + (lane >> 4) * 8) * 2;

    for (int tix = 0; tix < nj; tix++) {
        const int kt = (jstart + tix) * 64;
        const int st = tix & 1;

        if (tix + 1 < nj) {
            const int ktn = kt + 64;
            const uint32_t soff = oKV + (st ^ 1) * AKV_B;
#pragma unroll
            for (int i = 0; i < 16; i++) {
                int idx = i * 128 + tid;
                int t = idx >> 9, r = (idx >> 3) & 63, cc = idx & 7;
                cpa16(sb + soff + t * ATILE_B + (uint32_t)(r * QSTR + cc * 8) * 2,
                      kvsrc[t] + (size_t)(ktn + r) * 64 + cc * 8);
            }
            asm volatile("cp.async.commit_group;");
            asm volatile("cp.async.wait_group 1;");
        } else {
            asm volatile("cp.async.wait_group 0;");
        }
        __syncthreads();

        const uint32_t sKh = sb + oKV + st * AKV_B;
        const uint32_t sKl = sKh + ATILE_B;
        const uint32_t sVh = sKh + 2 * ATILE_B;
        const uint32_t sVl = sKh + 3 * ATILE_B;

        float s[8][4];
#pragma unroll
        for (int jb = 0; jb < 8; jb++)
#pragma unroll
            for (int d = 0; d < 4; d++) s[jb][d] = 0.f;

        {
            uint32_t khf[2][4], klf[2][4];
            ldsm_x4(khf[0], sKh + kaddr0);
            ldsm_x4(klf[0], sKl + kaddr0);
#pragma unroll
            for (int ix = 0; ix < 16; ix++) {
                const int c  = ix >> 2;
                const int nt = ix & 3;
                const int cur = ix & 1;
                if (ix < 15) {
                    const int cn  = (ix + 1) >> 2;
                    const int ntn = (ix + 1) & 3;
                    const uint32_t noff = (uint32_t)(ntn * 16 * QSTR * 2) + cn * 32;
                    ldsm_x4(khf[cur ^ 1], sKh + kaddr0 + noff);
                    ldsm_x4(klf[cur ^ 1], sKl + kaddr0 + noff);
                }
                mma16816(s[nt * 2 + 0], fqh[c], &khf[cur][0]);
                mma16816(s[nt * 2 + 1], fqh[c], &khf[cur][2]);
                mma16816(s[nt * 2 + 0], fqh[c], &klf[cur][0]);
                mma16816(s[nt * 2 + 1], fqh[c], &klf[cur][2]);
                mma16816(s[nt * 2 + 0], fql[c], &khf[cur][0]);
                mma16816(s[nt * 2 + 1], fql[c], &khf[cur][2]);
            }
        }

        if (kt == q0 && kt < PAD) {
            const int cbase = kt + 2 * (lane & 3);
#pragma unroll
            for (int jb = 0; jb < 8; jb++) {
                const int c0 = cbase + jb * 8;
                s[jb][0] = (c0     > r1) ? s[jb][0] : -1e30f;
                s[jb][1] = (c0 + 1 > r1) ? s[jb][1] : -1e30f;
                s[jb][2] = (c0     > r1 + 8) ? s[jb][2] : -1e30f;
                s[jb][3] = (c0 + 1 > r1 + 8) ? s[jb][3] : -1e30f;
            }
        }

        float t1 = -1e30f, t2 = -1e30f;
#pragma unroll
        for (int jb = 0; jb < 8; jb++) {
            t1 = fmaxf(t1, fmaxf(s[jb][0], s[jb][1]));
            t2 = fmaxf(t2, fmaxf(s[jb][2], s[jb][3]));
        }
        t1 = fmaxf(t1, __shfl_xor_sync(0xffffffffu, t1, 1));
        t1 = fmaxf(t1, __shfl_xor_sync(0xffffffffu, t1, 2));
        t2 = fmaxf(t2, __shfl_xor_sync(0xffffffffu, t2, 1));
        t2 = fmaxf(t2, __shfl_xor_sync(0xffffffffu, t2, 2));

        const float mn1 = fmaxf(m1, t1);
        const float mn2 = fmaxf(m2, t2);
        const float a1 = __expf(m1 - mn1);
        const float a2 = __expf(m2 - mn2);
        m1 = mn1; m2 = mn2;

        float sum1 = 0.f, sum2 = 0.f;
#pragma unroll
        for (int jb = 0; jb < 8; jb++) {
            s[jb][0] = __expf(s[jb][0] - mn1);
            s[jb][1] = __expf(s[jb][1] - mn1);
            s[jb][2] = __expf(s[jb][2] - mn2);
            s[jb][3] = __expf(s[jb][3] - mn2);
            sum1 += s[jb][0] + s[jb][1];
            sum2 += s[jb][2] + s[jb][3];
        }
        sum1 += __shfl_xor_sync(0xffffffffu, sum1, 1);
        sum1 += __shfl_xor_sync(0xffffffffu, sum1, 2);
        sum2 += __shfl_xor_sync(0xffffffffu, sum2, 1);
        sum2 += __shfl_xor_sync(0xffffffffu, sum2, 2);
        l1 = l1 * a1 + sum1;
        l2 = l2 * a2 + sum2;

#pragma unroll
        for (int jb = 0; jb < 8; jb++) {
            acc[jb][0] *= a1; acc[jb][1] *= a1;
            acc[jb][2] *= a2; acc[jb][3] *= a2;
        }

        uint32_t fph[4][4], fpl[4][4];
#pragma unroll
        for (int c = 0; c < 4; c++) {
            const float* p0 = s[2 * c];
            const float* p1 = s[2 * c + 1];
            fph[c][0] = packbf(p0[0], p0[1]);
            fph[c][1] = packbf(p0[2], p0[3]);
            fph[c][2] = packbf(p1[0], p1[1]);
            fph[c][3] = packbf(p1[2], p1[3]);
#pragma unroll
            for (int r = 0; r < 4; r++) {
                __nv_bfloat162 hb = *(__nv_bfloat162*)&fph[c][r];
                const float* src = (r < 2) ? p0 : p1;
                const int o = (r & 1) * 2;
                fpl[c][r] = packbf(src[o] - __bfloat162float(hb.x),
                                   src[o + 1] - __bfloat162float(hb.y));
            }
        }

        {
            uint32_t vhf[2][4], vlf[2][4];
            ldsm_x4_t(vhf[0], sVh + vaddr0);
            ldsm_x4_t(vlf[0], sVl + vaddr0);
#pragma unroll
            for (int ix = 0; ix < 16; ix++) {
                const int c  = ix >> 2;
                const int ng = ix & 3;
                const int cur = ix & 1;
                if (ix < 15) {
                    const int cn  = (ix + 1) >> 2;
                    const int ngn = (ix + 1) & 3;
                    const uint32_t aoff = (uint32_t)(cn * 16 * QSTR * 2) + vaddr0
                                        + (uint32_t)(ngn * 16 * 2);
                    ldsm_x4_t(vhf[cur ^ 1], sVh + aoff);
                    ldsm_x4_t(vlf[cur ^ 1], sVl + aoff);
                }
                mma16816(acc[ng * 2 + 0], fph[c], &vhf[cur][0]);
                mma16816(acc[ng * 2 + 1], fph[c], &vhf[cur][2]);
                mma16816(acc[ng * 2 + 0], fph[c], &vlf[cur][0]);
                mma16816(acc[ng * 2 + 1], fph[c], &vlf[cur][2]);
                mma16816(acc[ng * 2 + 0], fpl[c], &vhf[cur][0]);
                mma16816(acc[ng * 2 + 1], fpl[c], &vhf[cur][2]);
            }
        }
        __syncthreads();
    }

    // ---- epilogue: write single fp16 into out-proj A buffer ----
    const int b = bh >> 4;
    const int hh = bh & 15;
    const float inv1 = 1.f / l1;
    const float inv2 = 1.f / l2;
    const size_t row1 = (size_t)(b * Ll) + r1;
    const int col0 = hh * 64 + 2 * (lane & 3);
    __half2* H1 = (__half2*)OA + row1 * (Dm / 2) + (col0 >> 1);
    __half2* H2 = H1 + 8 * (Dm / 2);
#pragma unroll
    for (int jb = 0; jb < 8; jb++) {
        H1[jb * 4] = __floats2half2_rn(acc[jb][0] * inv1, acc[jb][1] * inv1);
        H2[jb * 4] = __floats2half2_rn(acc[jb][2] * inv2, acc[jb][3] * inv2);
    }
}

// ---------------------------------------------------------------------------
// Launch
// Inputs (metadata order): x, pad_mask, Wqkv, bqkv, Wout, bout
// ---------------------------------------------------------------------------
extern "C" void kernel_launch(void* const* d_in, const int* in_sizes, int n_in,
                              void* d_out, int out_size)
{
    const float* x    = (const float*)d_in[0];
    const float* Wqkv = (const float*)d_in[2];
    const float* bqkv = (const float*)d_in[3];
    const float* Wout = (const float*)d_in[4];
    const float* bout = (const float*)d_in[5];
    float* out = (float*)d_out;

    __half *ax, *bw;
    __nv_bfloat16 *qh, *ql, *kh, *kl, *vh, *vl;
    float2* rt;
    cudaGetSymbolAddress((void**)&ax, g_ax);
    cudaGetSymbolAddress((void**)&bw, g_bw);
    cudaGetSymbolAddress((void**)&qh, g_qh);
    cudaGetSymbolAddress((void**)&ql, g_ql);
    cudaGetSymbolAddress((void**)&kh, g_kh);
    cudaGetSymbolAddress((void**)&kl, g_kl);
    cudaGetSymbolAddress((void**)&vh, g_vh);
    cudaGetSymbolAddress((void**)&vl, g_vl);
    cudaGetSymbolAddress((void**)&rt, g_rope);

    cudaFuncSetAttribute(gemm_mma_fp16<0>, cudaFuncAttributeMaxDynamicSharedMemorySize, GSMEM);
    cudaFuncSetAttribute(gemm_mma_fp16<1>, cudaFuncAttributeMaxDynamicSharedMemorySize, GSMEM);
    cudaFuncSetAttribute(attn_mma, cudaFuncAttributeMaxDynamicSharedMemorySize, ASMEM);

    // 1) rope table + convert x and Wqkv to fp16
    {
        rope_table<<<(Ll * 32 + 255) / 256, 256>>>(rt);
        int n2 = (Mrows * Dm) / 2;
        cvt_fp16<<<(n2 + 255) / 256, 256>>>(x, ax, n2);
        n2 = (QKVN * Dm) / 2;
        cvt_fp16<<<(n2 + 255) / 256, 256>>>(Wqkv, bw, n2);
    }
    // 2) QKV projection + bias + RoPE + bf16-split scatter
    {
        dim3 grid(QKVN / 128, Mrows / 128);
        gemm_mma_fp16<1><<<grid, 256, GSMEM>>>(ax, bw, bqkv, nullptr,
                                               qh, ql, kh, kl, vh, vl, rt,
                                               Mrows, QKVN, Dm);
    }
    // 3) attention (writes fp16 out-proj A directly)
    {
        dim3 grid(Ll / 64, Bb * Hh);
        attn_mma<<<grid, 128, ASMEM>>>(qh, ql, kh, kl, vh, vl, ax);
    }
    // 4) convert Wout (fp16)
    {
        int n2 = (Dm * Dm) / 2;
        cvt_fp16<<<(n2 + 255) / 256, 256>>>(Wout, bw, n2);
    }
    // 5) output projection + bias
    {
        dim3 grid(Dm / 128, Mrows / 128);
        gemm_mma_fp16<0><<<grid, 256, GSMEM>>>(ax, bw, bout, out,
                                               nullptr, nullptr, nullptr, nullptr,
                                               nullptr, nullptr, nullptr,
                                               Mrows, Dm, Dm);
    }
}

// round 16
// speedup vs baseline: 1.8945x; 1.1913x over previous
#include <cuda_runtime.h>
#include <cuda_bf16.h>
#include <cuda_fp16.h>
#include <cstdint>
#include <math.h>

// Problem constants (fixed by the dataset)
#define Bb   2
#define Ll   2048
#define Dm   1024
#define Hh   16
#define DhD  64
#define PAD  1536
#define Mrows (Bb * Ll)          // 4096
#define QKVN  (3 * Dm)           // 3072

// ---------------------------------------------------------------------------
// Scratch (device globals; no runtime allocation allowed)
// ---------------------------------------------------------------------------
__device__ __half g_ax[(size_t)Mrows * Dm];
__device__ __half g_bw[(size_t)QKVN * Dm];
#define QKVSZ ((size_t)Bb * Hh * Ll * DhD)
// fp16 attention operands: q hi/lo (pre-scaled by 1/8), k single, v hi/lo
__device__ __half g_qh[QKVSZ], g_ql[QKVSZ];
__device__ __half g_ks[QKVSZ];
__device__ __half g_vh[QKVSZ], g_vl[QKVSZ];
__device__ float2 g_rope[Ll * 32];

// ---------------------------------------------------------------------------
// mma.sync helpers
// ---------------------------------------------------------------------------
__device__ __forceinline__ uint32_t smem_u32(const void* p) {
    uint32_t a;
    asm("{ .reg .u64 t; cvta.to.shared.u64 t, %1; cvt.u32.u64 %0, t; }" : "=r"(a) : "l"(p));
    return a;
}
__device__ __forceinline__ void ldsm_x4(uint32_t r[4], uint32_t addr) {
    asm volatile("ldmatrix.sync.aligned.m8n8.x4.shared.b16 {%0,%1,%2,%3}, [%4];"
                 : "=r"(r[0]), "=r"(r[1]), "=r"(r[2]), "=r"(r[3]) : "r"(addr));
}
__device__ __forceinline__ void ldsm_x4_t(uint32_t r[4], uint32_t addr) {
    asm volatile("ldmatrix.sync.aligned.m8n8.x4.trans.shared.b16 {%0,%1,%2,%3}, [%4];"
                 : "=r"(r[0]), "=r"(r[1]), "=r"(r[2]), "=r"(r[3]) : "r"(addr));
}
// fp16 mma (fp32 accumulate)
__device__ __forceinline__ void mma16816h(float c[4], const uint32_t a[4], const uint32_t b[2]) {
    asm("mma.sync.aligned.m16n8k16.row.col.f32.f16.f16.f32 "
        "{%0,%1,%2,%3}, {%4,%5,%6,%7}, {%8,%9}, {%0,%1,%2,%3};"
        : "+f"(c[0]), "+f"(c[1]), "+f"(c[2]), "+f"(c[3])
        : "r"(a[0]), "r"(a[1]), "r"(a[2]), "r"(a[3]), "r"(b[0]), "r"(b[1]));
}
__device__ __forceinline__ void cpa16(uint32_t dst, const void* src) {
    asm volatile("cp.async.cg.shared.global [%0], [%1], 16;" :: "r"(dst), "l"(src));
}
__device__ __forceinline__ uint32_t packh(float lo, float hi) {
    uint32_t r;
    asm("cvt.rn.f16x2.f32 %0, %1, %2;" : "=r"(r) : "f"(hi), "f"(lo));
    return r;
}
__device__ __forceinline__ void split2h(float2 v, __half2& h, __half2& l) {
    h = __floats2half2_rn(v.x, v.y);
    float2 hf = __half22float2(h);
    l = __floats2half2_rn(v.x - hf.x, v.y - hf.y);
}

// ---------------------------------------------------------------------------
// Kernel: fp32 -> fp16 convert
// ---------------------------------------------------------------------------
__global__ __launch_bounds__(256)
void cvt_fp16(const float* __restrict__ X, __half* __restrict__ H, int n2)
{
    int i = blockIdx.x * blockDim.x + threadIdx.x;
    if (i >= n2) return;
    float2 x = ((const float2*)X)[i];
    ((__half2*)H)[i] = __floats2half2_rn(x.x, x.y);
}

// ---------------------------------------------------------------------------
// Kernel: RoPE cos/sin table
// ---------------------------------------------------------------------------
__global__ __launch_bounds__(256)
void rope_table(float2* __restrict__ T)
{
    int idx = blockIdx.x * blockDim.x + threadIdx.x;
    if (idx >= Ll * 32) return;
    const int l = idx >> 5, j = idx & 31;
    const float inv_freq = __expf(-(float)j * (9.210340371976184f / 32.0f));
    float s, c;
    sincosf((float)l * inv_freq, &s, &c);
    T[idx] = make_float2(c, s);
}

// ---------------------------------------------------------------------------
// fp16 GEMM: C[M,N] = A[M,K] * B[N,K]^T + bias, KC=64.
// EPI=0: fp32 C+bias. EPI=1: fused bias+RoPE+fp16 scatter to q(hi/lo)/k/v(hi/lo).
// ---------------------------------------------------------------------------
#define PADW 72                      // 64 halfs + 8 pad -> 144B row stride
#define KC   64
#define TILE_BYTES (128 * PADW * 2)  // 18432
#define STAGE_BYTES (2 * TILE_BYTES) // 36864
#define GSMEM (2 * STAGE_BYTES)      // 73728

template<int EPI>
__global__ __launch_bounds__(256, 2)
void gemm_mma_fp16(const __half* __restrict__ A, const __half* __restrict__ Bw,
                   const float* __restrict__ bias, float* __restrict__ C,
                   __half* __restrict__ Qh, __half* __restrict__ Ql,
                   __half* __restrict__ Ks,
                   __half* __restrict__ Vh, __half* __restrict__ Vl,
                   const float2* __restrict__ Rt,
                   int M, int N, int K)
{
    extern __shared__ char dsm[];
    const uint32_t sbase = smem_u32(dsm);

    const int tid  = threadIdx.x;
    const int lane = tid & 31;
    const int wid  = tid >> 5;
    const int wm   = wid & 3;
    const int wn   = wid >> 2;
    const int m0   = blockIdx.y * 128;
    const int n0   = blockIdx.x * 128;

    float c[2][8][4];
#pragma unroll
    for (int i = 0; i < 2; i++)
#pragma unroll
        for (int j = 0; j < 8; j++)
#pragma unroll
            for (int q = 0; q < 4; q++) c[i][j][q] = 0.f;

    const int r0  = tid >> 3;           // 0..31
    const int cc8 = (tid & 7) * 8;
    const __half* srcA = A  + (size_t)(m0 + r0) * K + cc8;
    const __half* srcB = Bw + (size_t)(n0 + r0) * K + cc8;
    const uint32_t dstA = sbase + (uint32_t)(r0 * PADW + cc8) * 2;
    const uint32_t dstB = dstA + (uint32_t)TILE_BYTES;
    const size_t rstep = (size_t)32 * K;
    const uint32_t dstep = (uint32_t)(32 * PADW * 2);

    const int arow = wm * 32 + (lane & 15);
    const int acol = (lane >> 4) * 8;
    const int brow = wn * 64 + ((lane >> 4) << 3) + (lane & 7);
    const int bcol = ((lane >> 3) & 1) * 8;
    const uint32_t aA = sbase + 0 * TILE_BYTES + (uint32_t)(arow * PADW + acol) * 2;
    const uint32_t aB = sbase + 1 * TILE_BYTES + (uint32_t)(brow * PADW + bcol) * 2;

    const int nch = K / KC;   // 16

#pragma unroll
    for (int i = 0; i < 4; i++) {
        cpa16(dstA + i * dstep, srcA + (size_t)i * rstep);
        cpa16(dstB + i * dstep, srcB + (size_t)i * rstep);
    }
    asm volatile("cp.async.commit_group;");

    for (int s = 0; s < nch; s++) {
        if (s + 1 < nch) {
            const uint32_t stoff = ((s + 1) & 1) * (uint32_t)STAGE_BYTES;
            const int koff = (s + 1) * KC;
#pragma unroll
            for (int i = 0; i < 4; i++) {
                cpa16(dstA + stoff + i * dstep, srcA + koff + (size_t)i * rstep);
                cpa16(dstB + stoff + i * dstep, srcB + koff + (size_t)i * rstep);
            }
            asm volatile("cp.async.commit_group;");
            asm volatile("cp.async.wait_group 1;");
        } else {
            asm volatile("cp.async.wait_group 0;");
        }
        __syncthreads();

        const uint32_t stoff = (s & 1) * (uint32_t)STAGE_BYTES;
#pragma unroll
        for (int ks = 0; ks < 4; ks++) {
            const uint32_t kb = (uint32_t)(ks * 16 * 2);
            uint32_t ahf[2][4];
#pragma unroll
            for (int mt = 0; mt < 2; mt++)
                ldsm_x4(ahf[mt], aA + stoff + (uint32_t)(mt * 16 * PADW * 2) + kb);
            uint32_t bwf[2][4];
            ldsm_x4(bwf[0], aB + stoff + kb);
#pragma unroll
            for (int nt = 0; nt < 4; nt++) {
                const int cur = nt & 1;
                if (nt < 3) {
                    const uint32_t noff = stoff + (uint32_t)((nt + 1) * 16 * PADW * 2) + kb;
                    ldsm_x4(bwf[cur ^ 1], aB + noff);
                }
                mma16816h(c[0][nt * 2 + 0], ahf[0], &bwf[cur][0]);
                mma16816h(c[0][nt * 2 + 1], ahf[0], &bwf[cur][2]);
                mma16816h(c[1][nt * 2 + 0], ahf[1], &bwf[cur][0]);
                mma16816h(c[1][nt * 2 + 1], ahf[1], &bwf[cur][2]);
            }
        }
        __syncthreads();
    }

#pragma unroll
    for (int mt = 0; mt < 2; mt++) {
        const int mrow = m0 + wm * 32 + mt * 16 + (lane >> 2);
#pragma unroll
        for (int n8 = 0; n8 < 8; n8++) {
            const int ncol = n0 + wn * 64 + n8 * 8 + 2 * (lane & 3);
            float2 bb = *(const float2*)(bias + ncol);
            if (EPI == 0) {
                float2 o0, o1;
                o0.x = c[mt][n8][0] + bb.x; o0.y = c[mt][n8][1] + bb.y;
                o1.x = c[mt][n8][2] + bb.x; o1.y = c[mt][n8][3] + bb.y;
                *(float2*)&C[(size_t)mrow * N + ncol]       = o0;
                *(float2*)&C[(size_t)(mrow + 8) * N + ncol] = o1;
            } else {
                const int sec  = ncol >> 10;        // 0=q, 1=k, 2=v
                const int hcol = ncol & 1023;
                const int hh   = hcol >> 6;
                const int j    = (hcol & 63) >> 1;
#pragma unroll
                for (int r = 0; r < 2; r++) {
                    const int mr = mrow + r * 8;
                    const int l  = mr & (Ll - 1);
                    const int b  = mr >> 11;
                    float2 v;
                    v.x = c[mt][n8][2 * r]     + bb.x;
                    v.y = c[mt][n8][2 * r + 1] + bb.y;
                    const size_t base = ((size_t)(b * Hh + hh) * Ll + l) * 32 + j;
                    if (sec < 2) {
                        const float2 cs = Rt[l * 32 + j];
                        float nx = v.x * cs.x - v.y * cs.y;
                        float ny = v.x * cs.y + v.y * cs.x;
                        if (sec == 0) {
                            nx *= 0.125f; ny *= 0.125f;
                            __half2 hv, lv;
                            split2h(make_float2(nx, ny), hv, lv);
                            ((__half2*)Qh)[base] = hv;
                            ((__half2*)Ql)[base] = lv;
                        } else {
                            ((__half2*)Ks)[base] = __floats2half2_rn(nx, ny);
                        }
                    } else {
                        __half2 hv, lv;
                        split2h(v, hv, lv);
                        ((__half2*)Vh)[base] = hv;
                        ((__half2*)Vl)[base] = lv;
                    }
                }
            }
        }
    }
}

// ---------------------------------------------------------------------------
// Flash attention, fp16 asymmetric splits (inverted mask):
//   S = (Qh+Ql)·K  (K single fp16, 2 passes)
//   O = P·(Vh+Vl)  (P single fp16, 2 passes)
// KV stage = 3 tiles (K, Vh, Vl). Epilogue writes fp16 out-proj A.
// ---------------------------------------------------------------------------
#define QSTR 72
#define ATILE_B (64 * QSTR * 2)        // 9216
#define AKV_B   (3 * ATILE_B)          // 27648 per stage
#define ASMEM (2 * ATILE_B + 2 * AKV_B) // 73728

__global__ __launch_bounds__(128, 2)
void attn_mma(const __half* __restrict__ Qh, const __half* __restrict__ Ql,
              const __half* __restrict__ Ks,
              const __half* __restrict__ Vh, const __half* __restrict__ Vl,
              __half* __restrict__ OA)
{
    extern __shared__ char sm[];
    const uint32_t sb = smem_u32(sm);
    const int bh  = blockIdx.y;
    const int qt  = blockIdx.x;
    const int q0  = qt * 64;
    const int tid = threadIdx.x;
    const int lane = tid & 31;
    const int wid  = tid >> 5;

    const uint32_t oQ  = 0;
    const uint32_t oKV = 2 * ATILE_B;

    // ---- Q loads (group 0): qh, ql tiles ----
    {
        const __half* qsrc[2] = { Qh + ((size_t)bh * Ll + q0) * 64,
                                  Ql + ((size_t)bh * Ll + q0) * 64 };
#pragma unroll
        for (int i = 0; i < 8; i++) {
            int idx = i * 128 + tid;
            int t = idx >> 9, r = (idx >> 3) & 63, cc = idx & 7;
            cpa16(sb + oQ + t * ATILE_B + (uint32_t)(r * QSTR + cc * 8) * 2,
                  qsrc[t] + (size_t)r * 64 + cc * 8);
        }
        asm volatile("cp.async.commit_group;");
    }

    const int jstart = (qt < 24) ? qt : 24;
    const int nj = 32 - jstart;

    const __half* kvsrc[3] = {
        Ks + (size_t)bh * Ll * 64,
        Vh + (size_t)bh * Ll * 64,
        Vl + (size_t)bh * Ll * 64 };

    // ---- KV stage 0 (group 1): 3 tiles x 512 chunks ----
    {
        const int kt = jstart * 64;
#pragma unroll
        for (int i = 0; i < 12; i++) {
            int idx = i * 128 + tid;
            int t = idx >> 9, r = (idx >> 3) & 63, cc = idx & 7;
            cpa16(sb + oKV + t * ATILE_B + (uint32_t)(r * QSTR + cc * 8) * 2,
                  kvsrc[t] + (size_t)(kt + r) * 64 + cc * 8);
        }
        asm volatile("cp.async.commit_group;");
    }

    asm volatile("cp.async.wait_group 1;");
    __syncthreads();

    uint32_t fqh[4][4], fql[4][4];
    {
        const uint32_t qaddr = sb + oQ +
            (uint32_t)((wid * 16 + (lane & 15)) * QSTR + (lane >> 4) * 8) * 2;
#pragma unroll
        for (int c = 0; c < 4; c++) {
            ldsm_x4(fqh[c], qaddr + c * 32);
            ldsm_x4(fql[c], qaddr + ATILE_B + c * 32);
        }
    }

    float m1 = -5e29f, m2 = -5e29f, l1 = 0.f, l2 = 0.f;
    float acc[8][4];
#pragma unroll
    for (int j = 0; j < 8; j++)
#pragma unroll
        for (int d = 0; d < 4; d++) acc[j][d] = 0.f;

    const int r1 = q0 + wid * 16 + (lane >> 2);

    const uint32_t kaddr0 = (uint32_t)((((lane >> 4) << 3) + (lane & 7)) * QSTR
                                        + ((lane >> 3) & 1) * 8) * 2;
    const uint32_t vaddr0 = (uint32_t)((lane & 15) * QSTR + (lane >> 4) * 8) * 2;

    for (int tix = 0; tix < nj; tix++) {
        const int kt = (jstart + tix) * 64;
        const int st = tix & 1;

        if (tix + 1 < nj) {
            const int ktn = kt + 64;
            const uint32_t soff = oKV + (st ^ 1) * AKV_B;
#pragma unroll
            for (int i = 0; i < 12; i++) {
                int idx = i * 128 + tid;
                int t = idx >> 9, r = (idx >> 3) & 63, cc = idx & 7;
                cpa16(sb + soff + t * ATILE_B + (uint32_t)(r * QSTR + cc * 8) * 2,
                      kvsrc[t] + (size_t)(ktn + r) * 64 + cc * 8);
            }
            asm volatile("cp.async.commit_group;");
            asm volatile("cp.async.wait_group 1;");
        } else {
            asm volatile("cp.async.wait_group 0;");
        }
        __syncthreads();

        const uint32_t sK  = sb + oKV + st * AKV_B;
        const uint32_t sVh = sK + ATILE_B;
        const uint32_t sVl = sK + 2 * ATILE_B;

        // ---- S = (Qh+Ql) K^T, pipelined K fragments ----
        float s[8][4];
#pragma unroll
        for (int jb = 0; jb < 8; jb++)
#pragma unroll
            for (int d = 0; d < 4; d++) s[jb][d] = 0.f;

        {
            uint32_t khf[2][4];
            ldsm_x4(khf[0], sK + kaddr0);
#pragma unroll
            for (int ix = 0; ix < 16; ix++) {
                const int c  = ix >> 2;
                const int nt = ix & 3;
                const int cur = ix & 1;
                if (ix < 15) {
                    const int cn  = (ix + 1) >> 2;
                    const int ntn = (ix + 1) & 3;
                    const uint32_t noff = (uint32_t)(ntn * 16 * QSTR * 2) + cn * 32;
                    ldsm_x4(khf[cur ^ 1], sK + kaddr0 + noff);
                }
                mma16816h(s[nt * 2 + 0], fqh[c], &khf[cur][0]);
                mma16816h(s[nt * 2 + 1], fqh[c], &khf[cur][2]);
                mma16816h(s[nt * 2 + 0], fql[c], &khf[cur][0]);
                mma16816h(s[nt * 2 + 1], fql[c], &khf[cur][2]);
            }
        }

        if (kt == q0 && kt < PAD) {
            const int cbase = kt + 2 * (lane & 3);
#pragma unroll
            for (int jb = 0; jb < 8; jb++) {
                const int c0 = cbase + jb * 8;
                s[jb][0] = (c0     > r1) ? s[jb][0] : -1e30f;
                s[jb][1] = (c0 + 1 > r1) ? s[jb][1] : -1e30f;
                s[jb][2] = (c0     > r1 + 8) ? s[jb][2] : -1e30f;
                s[jb][3] = (c0 + 1 > r1 + 8) ? s[jb][3] : -1e30f;
            }
        }

        float t1 = -1e30f, t2 = -1e30f;
#pragma unroll
        for (int jb = 0; jb < 8; jb++) {
            t1 = fmaxf(t1, fmaxf(s[jb][0], s[jb][1]));
            t2 = fmaxf(t2, fmaxf(s[jb][2], s[jb][3]));
        }
        t1 = fmaxf(t1, __shfl_xor_sync(0xffffffffu, t1, 1));
        t1 = fmaxf(t1, __shfl_xor_sync(0xffffffffu, t1, 2));
        t2 = fmaxf(t2, __shfl_xor_sync(0xffffffffu, t2, 1));
        t2 = fmaxf(t2, __shfl_xor_sync(0xffffffffu, t2, 2));

        const float mn1 = fmaxf(m1, t1);
        const float mn2 = fmaxf(m2, t2);
        const float a1 = __expf(m1 - mn1);
        const float a2 = __expf(m2 - mn2);
        m1 = mn1; m2 = mn2;

        float sum1 = 0.f, sum2 = 0.f;
#pragma unroll
        for (int jb = 0; jb < 8; jb++) {
            s[jb][0] = __expf(s[jb][0] - mn1);
            s[jb][1] = __expf(s[jb][1] - mn1);
            s[jb][2] = __expf(s[jb][2] - mn2);
            s[jb][3] = __expf(s[jb][3] - mn2);
            sum1 += s[jb][0] + s[jb][1];
            sum2 += s[jb][2] + s[jb][3];
        }
        sum1 += __shfl_xor_sync(0xffffffffu, sum1, 1);
        sum1 += __shfl_xor_sync(0xffffffffu, sum1, 2);
        sum2 += __shfl_xor_sync(0xffffffffu, sum2, 1);
        sum2 += __shfl_xor_sync(0xffffffffu, sum2, 2);
        l1 = l1 * a1 + sum1;
        l2 = l2 * a2 + sum2;

#pragma unroll
        for (int jb = 0; jb < 8; jb++) {
            acc[jb][0] *= a1; acc[jb][1] *= a1;
            acc[jb][2] *= a2; acc[jb][3] *= a2;
        }

        // ---- P fragments: single fp16 ----
        uint32_t fph[4][4];
#pragma unroll
        for (int c = 0; c < 4; c++) {
            const float* p0 = s[2 * c];
            const float* p1 = s[2 * c + 1];
            fph[c][0] = packh(p0[0], p0[1]);
            fph[c][1] = packh(p0[2], p0[3]);
            fph[c][2] = packh(p1[0], p1[1]);
            fph[c][3] = packh(p1[2], p1[3]);
        }

        // ---- O += P (Vh+Vl), pipelined V fragments ----
        {
            uint32_t vhf[2][4], vlf[2][4];
            ldsm_x4_t(vhf[0], sVh + vaddr0);
            ldsm_x4_t(vlf[0], sVl + vaddr0);
#pragma unroll
            for (int ix = 0; ix < 16; ix++) {
                const int c  = ix >> 2;
                const int ng = ix & 3;
                const int cur = ix & 1;
                if (ix < 15) {
                    const int cn  = (ix + 1) >> 2;
                    const int ngn = (ix + 1) & 3;
                    const uint32_t aoff = (uint32_t)(cn * 16 * QSTR * 2) + vaddr0
                                        + (uint32_t)(ngn * 16 * 2);
                    ldsm_x4_t(vhf[cur ^ 1], sVh + aoff);
                    ldsm_x4_t(vlf[cur ^ 1], sVl + aoff);
                }
                mma16816h(acc[ng * 2 + 0], fph[c], &vhf[cur][0]);
                mma16816h(acc[ng * 2 + 1], fph[c], &vhf[cur][2]);
                mma16816h(acc[ng * 2 + 0], fph[c], &vlf[cur][0]);
                mma16816h(acc[ng * 2 + 1], fph[c], &vlf[cur][2]);
            }
        }
        __syncthreads();
    }

    // ---- epilogue: write single fp16 into out-proj A buffer ----
    const int b = bh >> 4;
    const int hh = bh & 15;
    const float inv1 = 1.f / l1;
    const float inv2 = 1.f / l2;
    const size_t row1 = (size_t)(b * Ll) + r1;
    const int col0 = hh * 64 + 2 * (lane & 3);
    __half2* H1 = (__half2*)OA + row1 * (Dm / 2) + (col0 >> 1);
    __half2* H2 = H1 + 8 * (Dm / 2);
#pragma unroll
    for (int jb = 0; jb < 8; jb++) {
        H1[jb * 4] = __floats2half2_rn(acc[jb][0] * inv1, acc[jb][1] * inv1);
        H2[jb * 4] = __floats2half2_rn(acc[jb][2] * inv2, acc[jb][3] * inv2);
    }
}

// ---------------------------------------------------------------------------
// Launch
// Inputs (metadata order): x, pad_mask, Wqkv, bqkv, Wout, bout
// ---------------------------------------------------------------------------
extern "C" void kernel_launch(void* const* d_in, const int* in_sizes, int n_in,
                              void* d_out, int out_size)
{
    const float* x    = (const float*)d_in[0];
    const float* Wqkv = (const float*)d_in[2];
    const float* bqkv = (const float*)d_in[3];
    const float* Wout = (const float*)d_in[4];
    const float* bout = (const float*)d_in[5];
    float* out = (float*)d_out;

    __half *ax, *bw, *qh, *ql, *ks, *vh, *vl;
    float2* rt;
    cudaGetSymbolAddress((void**)&ax, g_ax);
    cudaGetSymbolAddress((void**)&bw, g_bw);
    cudaGetSymbolAddress((void**)&qh, g_qh);
    cudaGetSymbolAddress((void**)&ql, g_ql);
    cudaGetSymbolAddress((void**)&ks, g_ks);
    cudaGetSymbolAddress((void**)&vh, g_vh);
    cudaGetSymbolAddress((void**)&vl, g_vl);
    cudaGetSymbolAddress((void**)&rt, g_rope);

    cudaFuncSetAttribute(gemm_mma_fp16<0>, cudaFuncAttributeMaxDynamicSharedMemorySize, GSMEM);
    cudaFuncSetAttribute(gemm_mma_fp16<1>, cudaFuncAttributeMaxDynamicSharedMemorySize, GSMEM);
    cudaFuncSetAttribute(attn_mma, cudaFuncAttributeMaxDynamicSharedMemorySize, ASMEM);

    // 1) rope table + convert x and Wqkv to fp16
    {
        rope_table<<<(Ll * 32 + 255) / 256, 256>>>(rt);
        int n2 = (Mrows * Dm) / 2;
        cvt_fp16<<<(n2 + 255) / 256, 256>>>(x, ax, n2);
        n2 = (QKVN * Dm) / 2;
        cvt_fp16<<<(n2 + 255) / 256, 256>>>(Wqkv, bw, n2);
    }
    // 2) QKV projection + bias + RoPE + fp16 scatter
    {
        dim3 grid(QKVN / 128, Mrows / 128);
        gemm_mma_fp16<1><<<grid, 256, GSMEM>>>(ax, bw, bqkv, nullptr,
                                               qh, ql, ks, vh, vl, rt,
                                               Mrows, QKVN, Dm);
    }
    // 3) attention (writes fp16 out-proj A directly)
    {
        dim3 grid(Ll / 64, Bb * Hh);
        attn_mma<<<grid, 128, ASMEM>>>(qh, ql, ks, vh, vl, ax);
    }
    // 4) convert Wout (fp16)
    {
        int n2 = (Dm * Dm) / 2;
        cvt_fp16<<<(n2 + 255) / 256, 256>>>(Wout, bw, n2);
    }
    // 5) output projection + bias
    {
        dim3 grid(Dm / 128, Mrows / 128);
        gemm_mma_fp16<0><<<grid, 256, GSMEM>>>(ax, bw, bout, out,
                                               nullptr, nullptr, nullptr,
                                               nullptr, nullptr, nullptr,
                                               Mrows, Dm, Dm);
    }
}

// round 17
// speedup vs baseline: 2.2829x; 1.2050x over previous
#include <cuda_runtime.h>
#include <cuda_bf16.h>
#include <cuda_fp16.h>
#include <cstdint>
#include <math.h>

// Problem constants (fixed by the dataset)
#define Bb   2
#define Ll   2048
#define Dm   1024
#define Hh   16
#define DhD  64
#define PAD  1536
#define Mrows (Bb * Ll)          // 4096
#define QKVN  (3 * Dm)           // 3072

// ---------------------------------------------------------------------------
// Scratch (device globals; no runtime allocation allowed)
// ---------------------------------------------------------------------------
__device__ __half g_ax[(size_t)Mrows * Dm];
__device__ __half g_bw[(size_t)QKVN * Dm];
#define QKVSZ ((size_t)Bb * Hh * Ll * DhD)
// fp16 attention operands: q (pre-scaled by 1/8), k, v — all single fp16
__device__ __half g_qs[QKVSZ];
__device__ __half g_ks[QKVSZ];
__device__ __half g_vs[QKVSZ];
__device__ float2 g_rope[Ll * 32];

// ---------------------------------------------------------------------------
// mma.sync helpers
// ---------------------------------------------------------------------------
__device__ __forceinline__ uint32_t smem_u32(const void* p) {
    uint32_t a;
    asm("{ .reg .u64 t; cvta.to.shared.u64 t, %1; cvt.u32.u64 %0, t; }" : "=r"(a) : "l"(p));
    return a;
}
__device__ __forceinline__ void ldsm_x4(uint32_t r[4], uint32_t addr) {
    asm volatile("ldmatrix.sync.aligned.m8n8.x4.shared.b16 {%0,%1,%2,%3}, [%4];"
                 : "=r"(r[0]), "=r"(r[1]), "=r"(r[2]), "=r"(r[3]) : "r"(addr));
}
__device__ __forceinline__ void ldsm_x4_t(uint32_t r[4], uint32_t addr) {
    asm volatile("ldmatrix.sync.aligned.m8n8.x4.trans.shared.b16 {%0,%1,%2,%3}, [%4];"
                 : "=r"(r[0]), "=r"(r[1]), "=r"(r[2]), "=r"(r[3]) : "r"(addr));
}
// fp16 mma (fp32 accumulate)
__device__ __forceinline__ void mma16816h(float c[4], const uint32_t a[4], const uint32_t b[2]) {
    asm("mma.sync.aligned.m16n8k16.row.col.f32.f16.f16.f32 "
        "{%0,%1,%2,%3}, {%4,%5,%6,%7}, {%8,%9}, {%0,%1,%2,%3};"
        : "+f"(c[0]), "+f"(c[1]), "+f"(c[2]), "+f"(c[3])
        : "r"(a[0]), "r"(a[1]), "r"(a[2]), "r"(a[3]), "r"(b[0]), "r"(b[1]));
}
__device__ __forceinline__ void cpa16(uint32_t dst, const void* src) {
    asm volatile("cp.async.cg.shared.global [%0], [%1], 16;" :: "r"(dst), "l"(src));
}
__device__ __forceinline__ uint32_t packh(float lo, float hi) {
    uint32_t r;
    asm("cvt.rn.f16x2.f32 %0, %1, %2;" : "=r"(r) : "f"(hi), "f"(lo));
    return r;
}

// ---------------------------------------------------------------------------
// Kernel: fp32 -> fp16 convert
// ---------------------------------------------------------------------------
__global__ __launch_bounds__(256)
void cvt_fp16(const float* __restrict__ X, __half* __restrict__ H, int n2)
{
    int i = blockIdx.x * blockDim.x + threadIdx.x;
    if (i >= n2) return;
    float2 x = ((const float2*)X)[i];
    ((__half2*)H)[i] = __floats2half2_rn(x.x, x.y);
}

// ---------------------------------------------------------------------------
// Kernel: RoPE cos/sin table
// ---------------------------------------------------------------------------
__global__ __launch_bounds__(256)
void rope_table(float2* __restrict__ T)
{
    int idx = blockIdx.x * blockDim.x + threadIdx.x;
    if (idx >= Ll * 32) return;
    const int l = idx >> 5, j = idx & 31;
    const float inv_freq = __expf(-(float)j * (9.210340371976184f / 32.0f));
    float s, c;
    sincosf((float)l * inv_freq, &s, &c);
    T[idx] = make_float2(c, s);
}

// ---------------------------------------------------------------------------
// fp16 GEMM: C[M,N] = A[M,K] * B[N,K]^T + bias, KC=64.
// EPI=0: fp32 C+bias. EPI=1: fused bias+RoPE+fp16 scatter to q/k/v (single).
// ---------------------------------------------------------------------------
#define PADW 72                      // 64 halfs + 8 pad -> 144B row stride
#define KC   64
#define TILE_BYTES (128 * PADW * 2)  // 18432
#define STAGE_BYTES (2 * TILE_BYTES) // 36864
#define GSMEM (2 * STAGE_BYTES)      // 73728

template<int EPI>
__global__ __launch_bounds__(256, 2)
void gemm_mma_fp16(const __half* __restrict__ A, const __half* __restrict__ Bw,
                   const float* __restrict__ bias, float* __restrict__ C,
                   __half* __restrict__ Qs, __half* __restrict__ Ks,
                   __half* __restrict__ Vs,
                   const float2* __restrict__ Rt,
                   int M, int N, int K)
{
    extern __shared__ char dsm[];
    const uint32_t sbase = smem_u32(dsm);

    const int tid  = threadIdx.x;
    const int lane = tid & 31;
    const int wid  = tid >> 5;
    const int wm   = wid & 3;
    const int wn   = wid >> 2;
    const int m0   = blockIdx.y * 128;
    const int n0   = blockIdx.x * 128;

    float c[2][8][4];
#pragma unroll
    for (int i = 0; i < 2; i++)
#pragma unroll
        for (int j = 0; j < 8; j++)
#pragma unroll
            for (int q = 0; q < 4; q++) c[i][j][q] = 0.f;

    const int r0  = tid >> 3;           // 0..31
    const int cc8 = (tid & 7) * 8;
    const __half* srcA = A  + (size_t)(m0 + r0) * K + cc8;
    const __half* srcB = Bw + (size_t)(n0 + r0) * K + cc8;
    const uint32_t dstA = sbase + (uint32_t)(r0 * PADW + cc8) * 2;
    const uint32_t dstB = dstA + (uint32_t)TILE_BYTES;
    const size_t rstep = (size_t)32 * K;
    const uint32_t dstep = (uint32_t)(32 * PADW * 2);

    const int arow = wm * 32 + (lane & 15);
    const int acol = (lane >> 4) * 8;
    const int brow = wn * 64 + ((lane >> 4) << 3) + (lane & 7);
    const int bcol = ((lane >> 3) & 1) * 8;
    const uint32_t aA = sbase + 0 * TILE_BYTES + (uint32_t)(arow * PADW + acol) * 2;
    const uint32_t aB = sbase + 1 * TILE_BYTES + (uint32_t)(brow * PADW + bcol) * 2;

    const int nch = K / KC;   // 16

#pragma unroll
    for (int i = 0; i < 4; i++) {
        cpa16(dstA + i * dstep, srcA + (size_t)i * rstep);
        cpa16(dstB + i * dstep, srcB + (size_t)i * rstep);
    }
    asm volatile("cp.async.commit_group;");

    for (int s = 0; s < nch; s++) {
        if (s + 1 < nch) {
            const uint32_t stoff = ((s + 1) & 1) * (uint32_t)STAGE_BYTES;
            const int koff = (s + 1) * KC;
#pragma unroll
            for (int i = 0; i < 4; i++) {
                cpa16(dstA + stoff + i * dstep, srcA + koff + (size_t)i * rstep);
                cpa16(dstB + stoff + i * dstep, srcB + koff + (size_t)i * rstep);
            }
            asm volatile("cp.async.commit_group;");
            asm volatile("cp.async.wait_group 1;");
        } else {
            asm volatile("cp.async.wait_group 0;");
        }
        __syncthreads();

        const uint32_t stoff = (s & 1) * (uint32_t)STAGE_BYTES;
#pragma unroll
        for (int ks = 0; ks < 4; ks++) {
            const uint32_t kb = (uint32_t)(ks * 16 * 2);
            uint32_t ahf[2][4];
#pragma unroll
            for (int mt = 0; mt < 2; mt++)
                ldsm_x4(ahf[mt], aA + stoff + (uint32_t)(mt * 16 * PADW * 2) + kb);
            uint32_t bwf[2][4];
            ldsm_x4(bwf[0], aB + stoff + kb);
#pragma unroll
            for (int nt = 0; nt < 4; nt++) {
                const int cur = nt & 1;
                if (nt < 3) {
                    const uint32_t noff = stoff + (uint32_t)((nt + 1) * 16 * PADW * 2) + kb;
                    ldsm_x4(bwf[cur ^ 1], aB + noff);
                }
                mma16816h(c[0][nt * 2 + 0], ahf[0], &bwf[cur][0]);
                mma16816h(c[0][nt * 2 + 1], ahf[0], &bwf[cur][2]);
                mma16816h(c[1][nt * 2 + 0], ahf[1], &bwf[cur][0]);
                mma16816h(c[1][nt * 2 + 1], ahf[1], &bwf[cur][2]);
            }
        }
        __syncthreads();
    }

#pragma unroll
    for (int mt = 0; mt < 2; mt++) {
        const int mrow = m0 + wm * 32 + mt * 16 + (lane >> 2);
#pragma unroll
        for (int n8 = 0; n8 < 8; n8++) {
            const int ncol = n0 + wn * 64 + n8 * 8 + 2 * (lane & 3);
            float2 bb = *(const float2*)(bias + ncol);
            if (EPI == 0) {
                float2 o0, o1;
                o0.x = c[mt][n8][0] + bb.x; o0.y = c[mt][n8][1] + bb.y;
                o1.x = c[mt][n8][2] + bb.x; o1.y = c[mt][n8][3] + bb.y;
                *(float2*)&C[(size_t)mrow * N + ncol]       = o0;
                *(float2*)&C[(size_t)(mrow + 8) * N + ncol] = o1;
            } else {
                const int sec  = ncol >> 10;        // 0=q, 1=k, 2=v
                const int hcol = ncol & 1023;
                const int hh   = hcol >> 6;
                const int j    = (hcol & 63) >> 1;
#pragma unroll
                for (int r = 0; r < 2; r++) {
                    const int mr = mrow + r * 8;
                    const int l  = mr & (Ll - 1);
                    const int b  = mr >> 11;
                    float2 v;
                    v.x = c[mt][n8][2 * r]     + bb.x;
                    v.y = c[mt][n8][2 * r + 1] + bb.y;
                    const size_t base = ((size_t)(b * Hh + hh) * Ll + l) * 32 + j;
                    if (sec < 2) {
                        const float2 cs = Rt[l * 32 + j];
                        float nx = v.x * cs.x - v.y * cs.y;
                        float ny = v.x * cs.y + v.y * cs.x;
                        if (sec == 0) {
                            nx *= 0.125f; ny *= 0.125f;
                            ((__half2*)Qs)[base] = __floats2half2_rn(nx, ny);
                        } else {
                            ((__half2*)Ks)[base] = __floats2half2_rn(nx, ny);
                        }
                    } else {
                        ((__half2*)Vs)[base] = __floats2half2_rn(v.x, v.y);
                    }
                }
            }
        }
    }
}

// ---------------------------------------------------------------------------
// Flash attention, all-single-fp16 operands (inverted mask):
//   S = Q·K^T, O = P·V  (fp32 accumulate, fp32 softmax)
// KV stage = 2 tiles (K, V). Epilogue writes fp16 out-proj A.
// ---------------------------------------------------------------------------
#define QSTR 72
#define ATILE_B (64 * QSTR * 2)        // 9216
#define AKV_B   (2 * ATILE_B)          // 18432 per stage
#define ASMEM (ATILE_B + 2 * AKV_B)    // 46080

__global__ __launch_bounds__(128, 2)
void attn_mma(const __half* __restrict__ Qs, const __half* __restrict__ Ks,
              const __half* __restrict__ Vs, __half* __restrict__ OA)
{
    extern __shared__ char sm[];
    const uint32_t sb = smem_u32(sm);
    const int bh  = blockIdx.y;
    const int qt  = blockIdx.x;
    const int q0  = qt * 64;
    const int tid = threadIdx.x;
    const int lane = tid & 31;
    const int wid  = tid >> 5;

    const uint32_t oQ  = 0;
    const uint32_t oKV = ATILE_B;

    // ---- Q load (group 0): 1 tile = 512 chunks ----
    {
        const __half* qsrc = Qs + ((size_t)bh * Ll + q0) * 64;
#pragma unroll
        for (int i = 0; i < 4; i++) {
            int idx = i * 128 + tid;
            int r = idx >> 3, cc = idx & 7;
            cpa16(sb + oQ + (uint32_t)(r * QSTR + cc * 8) * 2,
                  qsrc + (size_t)r * 64 + cc * 8);
        }
        asm volatile("cp.async.commit_group;");
    }

    const int jstart = (qt < 24) ? qt : 24;
    const int nj = 32 - jstart;

    const __half* kvsrc[2] = {
        Ks + (size_t)bh * Ll * 64,
        Vs + (size_t)bh * Ll * 64 };

    // ---- KV stage 0 (group 1): 2 tiles x 512 chunks ----
    {
        const int kt = jstart * 64;
#pragma unroll
        for (int i = 0; i < 8; i++) {
            int idx = i * 128 + tid;
            int t = idx >> 9, r = (idx >> 3) & 63, cc = idx & 7;
            cpa16(sb + oKV + t * ATILE_B + (uint32_t)(r * QSTR + cc * 8) * 2,
                  kvsrc[t] + (size_t)(kt + r) * 64 + cc * 8);
        }
        asm volatile("cp.async.commit_group;");
    }

    asm volatile("cp.async.wait_group 1;");
    __syncthreads();

    uint32_t fq[4][4];
    {
        const uint32_t qaddr = sb + oQ +
            (uint32_t)((wid * 16 + (lane & 15)) * QSTR + (lane >> 4) * 8) * 2;
#pragma unroll
        for (int c = 0; c < 4; c++)
            ldsm_x4(fq[c], qaddr + c * 32);
    }

    float m1 = -5e29f, m2 = -5e29f, l1 = 0.f, l2 = 0.f;
    float acc[8][4];
#pragma unroll
    for (int j = 0; j < 8; j++)
#pragma unroll
        for (int d = 0; d < 4; d++) acc[j][d] = 0.f;

    const int r1 = q0 + wid * 16 + (lane >> 2);

    const uint32_t kaddr0 = (uint32_t)((((lane >> 4) << 3) + (lane & 7)) * QSTR
                                        + ((lane >> 3) & 1) * 8) * 2;
    const uint32_t vaddr0 = (uint32_t)((lane & 15) * QSTR + (lane >> 4) * 8) * 2;

    for (int tix = 0; tix < nj; tix++) {
        const int kt = (jstart + tix) * 64;
        const int st = tix & 1;

        if (tix + 1 < nj) {
            const int ktn = kt + 64;
            const uint32_t soff = oKV + (st ^ 1) * AKV_B;
#pragma unroll
            for (int i = 0; i < 8; i++) {
                int idx = i * 128 + tid;
                int t = idx >> 9, r = (idx >> 3) & 63, cc = idx & 7;
                cpa16(sb + soff + t * ATILE_B + (uint32_t)(r * QSTR + cc * 8) * 2,
                      kvsrc[t] + (size_t)(ktn + r) * 64 + cc * 8);
            }
            asm volatile("cp.async.commit_group;");
            asm volatile("cp.async.wait_group 1;");
        } else {
            asm volatile("cp.async.wait_group 0;");
        }
        __syncthreads();

        const uint32_t sK = sb + oKV + st * AKV_B;
        const uint32_t sV = sK + ATILE_B;

        // ---- S = Q K^T, pipelined K fragments ----
        float s[8][4];
#pragma unroll
        for (int jb = 0; jb < 8; jb++)
#pragma unroll
            for (int d = 0; d < 4; d++) s[jb][d] = 0.f;

        {
            uint32_t khf[2][4];
            ldsm_x4(khf[0], sK + kaddr0);
#pragma unroll
            for (int ix = 0; ix < 16; ix++) {
                const int c  = ix >> 2;
                const int nt = ix & 3;
                const int cur = ix & 1;
                if (ix < 15) {
                    const int cn  = (ix + 1) >> 2;
                    const int ntn = (ix + 1) & 3;
                    const uint32_t noff = (uint32_t)(ntn * 16 * QSTR * 2) + cn * 32;
                    ldsm_x4(khf[cur ^ 1], sK + kaddr0 + noff);
                }
                mma16816h(s[nt * 2 + 0], fq[c], &khf[cur][0]);
                mma16816h(s[nt * 2 + 1], fq[c], &khf[cur][2]);
            }
        }

        if (kt == q0 && kt < PAD) {
            const int cbase = kt + 2 * (lane & 3);
#pragma unroll
            for (int jb = 0; jb < 8; jb++) {
                const int c0 = cbase + jb * 8;
                s[jb][0] = (c0     > r1) ? s[jb][0] : -1e30f;
                s[jb][1] = (c0 + 1 > r1) ? s[jb][1] : -1e30f;
                s[jb][2] = (c0     > r1 + 8) ? s[jb][2] : -1e30f;
                s[jb][3] = (c0 + 1 > r1 + 8) ? s[jb][3] : -1e30f;
            }
        }

        float t1 = -1e30f, t2 = -1e30f;
#pragma unroll
        for (int jb = 0; jb < 8; jb++) {
            t1 = fmaxf(t1, fmaxf(s[jb][0], s[jb][1]));
            t2 = fmaxf(t2, fmaxf(s[jb][2], s[jb][3]));
        }
        t1 = fmaxf(t1, __shfl_xor_sync(0xffffffffu, t1, 1));
        t1 = fmaxf(t1, __shfl_xor_sync(0xffffffffu, t1, 2));
        t2 = fmaxf(t2, __shfl_xor_sync(0xffffffffu, t2, 1));
        t2 = fmaxf(t2, __shfl_xor_sync(0xffffffffu, t2, 2));

        const float mn1 = fmaxf(m1, t1);
        const float mn2 = fmaxf(m2, t2);
        const float a1 = __expf(m1 - mn1);
        const float a2 = __expf(m2 - mn2);
        m1 = mn1; m2 = mn2;

        float sum1 = 0.f, sum2 = 0.f;
#pragma unroll
        for (int jb = 0; jb < 8; jb++) {
            s[jb][0] = __expf(s[jb][0] - mn1);
            s[jb][1] = __expf(s[jb][1] - mn1);
            s[jb][2] = __expf(s[jb][2] - mn2);
            s[jb][3] = __expf(s[jb][3] - mn2);
            sum1 += s[jb][0] + s[jb][1];
            sum2 += s[jb][2] + s[jb][3];
        }
        sum1 += __shfl_xor_sync(0xffffffffu, sum1, 1);
        sum1 += __shfl_xor_sync(0xffffffffu, sum1, 2);
        sum2 += __shfl_xor_sync(0xffffffffu, sum2, 1);
        sum2 += __shfl_xor_sync(0xffffffffu, sum2, 2);
        l1 = l1 * a1 + sum1;
        l2 = l2 * a2 + sum2;

#pragma unroll
        for (int jb = 0; jb < 8; jb++) {
            acc[jb][0] *= a1; acc[jb][1] *= a1;
            acc[jb][2] *= a2; acc[jb][3] *= a2;
        }

        // ---- P fragments: single fp16 ----
        uint32_t fph[4][4];
#pragma unroll
        for (int c = 0; c < 4; c++) {
            const float* p0 = s[2 * c];
            const float* p1 = s[2 * c + 1];
            fph[c][0] = packh(p0[0], p0[1]);
            fph[c][1] = packh(p0[2], p0[3]);
            fph[c][2] = packh(p1[0], p1[1]);
            fph[c][3] = packh(p1[2], p1[3]);
        }

        // ---- O += P V, pipelined V fragments ----
        {
            uint32_t vhf[2][4];
            ldsm_x4_t(vhf[0], sV + vaddr0);
#pragma unroll
            for (int ix = 0; ix < 16; ix++) {
                const int c  = ix >> 2;
                const int ng = ix & 3;
                const int cur = ix & 1;
                if (ix < 15) {
                    const int cn  = (ix + 1) >> 2;
                    const int ngn = (ix + 1) & 3;
                    const uint32_t aoff = (uint32_t)(cn * 16 * QSTR * 2) + vaddr0
                                        + (uint32_t)(ngn * 16 * 2);
                    ldsm_x4_t(vhf[cur ^ 1], sV + aoff);
                }
                mma16816h(acc[ng * 2 + 0], fph[c], &vhf[cur][0]);
                mma16816h(acc[ng * 2 + 1], fph[c], &vhf[cur][2]);
            }
        }
        __syncthreads();
    }

    // ---- epilogue: write single fp16 into out-proj A buffer ----
    const int b = bh >> 4;
    const int hh = bh & 15;
    const float inv1 = 1.f / l1;
    const float inv2 = 1.f / l2;
    const size_t row1 = (size_t)(b * Ll) + r1;
    const int col0 = hh * 64 + 2 * (lane & 3);
    __half2* H1 = (__half2*)OA + row1 * (Dm / 2) + (col0 >> 1);
    __half2* H2 = H1 + 8 * (Dm / 2);
#pragma unroll
    for (int jb = 0; jb < 8; jb++) {
        H1[jb * 4] = __floats2half2_rn(acc[jb][0] * inv1, acc[jb][1] * inv1);
        H2[jb * 4] = __floats2half2_rn(acc[jb][2] * inv2, acc[jb][3] * inv2);
    }
}

// ---------------------------------------------------------------------------
// Launch
// Inputs (metadata order): x, pad_mask, Wqkv, bqkv, Wout, bout
// ---------------------------------------------------------------------------
extern "C" void kernel_launch(void* const* d_in, const int* in_sizes, int n_in,
                              void* d_out, int out_size)
{
    const float* x    = (const float*)d_in[0];
    const float* Wqkv = (const float*)d_in[2];
    const float* bqkv = (const float*)d_in[3];
    const float* Wout = (const float*)d_in[4];
    const float* bout = (const float*)d_in[5];
    float* out = (float*)d_out;

    __half *ax, *bw, *qs, *ks, *vs;
    float2* rt;
    cudaGetSymbolAddress((void**)&ax, g_ax);
    cudaGetSymbolAddress((void**)&bw, g_bw);
    cudaGetSymbolAddress((void**)&qs, g_qs);
    cudaGetSymbolAddress((void**)&ks, g_ks);
    cudaGetSymbolAddress((void**)&vs, g_vs);
    cudaGetSymbolAddress((void**)&rt, g_rope);

    cudaFuncSetAttribute(gemm_mma_fp16<0>, cudaFuncAttributeMaxDynamicSharedMemorySize, GSMEM);
    cudaFuncSetAttribute(gemm_mma_fp16<1>, cudaFuncAttributeMaxDynamicSharedMemorySize, GSMEM);
    cudaFuncSetAttribute(attn_mma, cudaFuncAttributeMaxDynamicSharedMemorySize, ASMEM);

    // 1) rope table + convert x and Wqkv to fp16
    {
        rope_table<<<(Ll * 32 + 255) / 256, 256>>>(rt);
        int n2 = (Mrows * Dm) / 2;
        cvt_fp16<<<(n2 + 255) / 256, 256>>>(x, ax, n2);
        n2 = (QKVN * Dm) / 2;
        cvt_fp16<<<(n2 + 255) / 256, 256>>>(Wqkv, bw, n2);
    }
    // 2) QKV projection + bias + RoPE + fp16 scatter
    {
        dim3 grid(QKVN / 128, Mrows / 128);
        gemm_mma_fp16<1><<<grid, 256, GSMEM>>>(ax, bw, bqkv, nullptr,
                                               qs, ks, vs, rt,
                                               Mrows, QKVN, Dm);
    }
    // 3) attention (writes fp16 out-proj A directly)
    {
        dim3 grid(Ll / 64, Bb * Hh);
        attn_mma<<<grid, 128, ASMEM>>>(qs, ks, vs, ax);
    }
    // 4) convert Wout (fp16)
    {
        int n2 = (Dm * Dm) / 2;
        cvt_fp16<<<(n2 + 255) / 256, 256>>>(Wout, bw, n2);
    }
    // 5) output projection + bias
    {
        dim3 grid(Dm / 128, Mrows / 128);
        gemm_mma_fp16<0><<<grid, 256, GSMEM>>>(ax, bw, bout, out,
                                               nullptr, nullptr, nullptr, nullptr,
                                               Mrows, Dm, Dm);
    }
}